// round 2
// baseline (speedup 1.0000x reference)
#include <cuda_runtime.h>
#include <cstdint>

#define BB 2
#define SS 2048
#define HH 1024
#define NH 16
#define HD 64
#define QKV_ELEMS (BB*NH*SS*HD)   // 4,194,304

typedef unsigned long long ull;

// Scratch for projected q, k, v in [B, heads, S, hd] layout (16 MB each).
__device__ float g_q[QKV_ELEMS];
__device__ float g_k[QKV_ELEMS];
__device__ float g_v[QKV_ELEMS];

// ---------------------------------------------------------------------------
// Packed f32x2 helpers (sm_103a).  fma.rn.f32x2 is bit-exact IEEE fp32 FMA on
// each 32-bit half of a 64-bit register pair -> 2x fp32 FMA throughput with
// numerics identical to scalar FFMA.
// ---------------------------------------------------------------------------
__device__ __forceinline__ ull pack2(float x) {
    ull r; unsigned u = __float_as_uint(x);
    asm("mov.b64 %0, {%1, %1};" : "=l"(r) : "r"(u));
    return r;
}
__device__ __forceinline__ float2 unpack2(ull v) {
    unsigned lo, hi;
    asm("mov.b64 {%0, %1}, %2;" : "=r"(lo), "=r"(hi) : "l"(v));
    return make_float2(__uint_as_float(lo), __uint_as_float(hi));
}
__device__ __forceinline__ void ffma2(ull& d, ull a, ull b) {
    asm("fma.rn.f32x2 %0, %1, %2, %0;" : "+l"(d) : "l"(a), "l"(b));
}

// ---------------------------------------------------------------------------
// Kernel 1: fused projection GEMMs.  Y = X @ W^T + b for q,k,v (blockIdx.z),
// remapped to [B, heads, S, hd].  BM=128, BN=128, BK=16, 256 threads,
// 8x8 microtile via f32x2 (acc = 8 x 4 packed pairs along j).
// ---------------------------------------------------------------------------
__global__ __launch_bounds__(256) void proj_kernel(
    const float* __restrict__ Xq, const float* __restrict__ Xk,
    const float* __restrict__ Xv,
    const float* __restrict__ Wq, const float* __restrict__ Wk,
    const float* __restrict__ Wv,
    const float* __restrict__ bq, const float* __restrict__ bk,
    const float* __restrict__ bv,
    float* __restrict__ Yq, float* __restrict__ Yk, float* __restrict__ Yv)
{
    __shared__ float As[16][128];
    __shared__ float Bs[16][128];

    const float* X; const float* W; const float* bias; float* Y;
    if (blockIdx.z == 0)      { X = Xq; W = Wq; bias = bq; Y = Yq; }
    else if (blockIdx.z == 1) { X = Xk; W = Wk; bias = bk; Y = Yk; }
    else                      { X = Xv; W = Wv; bias = bv; Y = Yv; }

    const int r0 = blockIdx.y * 128;
    const int c0 = blockIdx.x * 128;
    const int t  = threadIdx.x;
    const int tx = t & 15;
    const int ty = t >> 4;

    ull acc[8][4];
#pragma unroll
    for (int i = 0; i < 8; i++)
#pragma unroll
        for (int j = 0; j < 4; j++) acc[i][j] = 0ull;

    for (int k0 = 0; k0 < HH; k0 += 16) {
#pragma unroll
        for (int u = 0; u < 2; u++) {
            int l = u * 256 + t;
            int r = l >> 2;
            int kq = l & 3;
            float4 v = *(const float4*)(X + (size_t)(r0 + r) * HH + k0 + kq * 4);
            As[kq*4+0][r] = v.x; As[kq*4+1][r] = v.y;
            As[kq*4+2][r] = v.z; As[kq*4+3][r] = v.w;
        }
#pragma unroll
        for (int u = 0; u < 2; u++) {
            int l = u * 256 + t;
            int c = l >> 2;
            int kq = l & 3;
            float4 v = *(const float4*)(W + (size_t)(c0 + c) * HH + k0 + kq * 4);
            Bs[kq*4+0][c] = v.x; Bs[kq*4+1][c] = v.y;
            Bs[kq*4+2][c] = v.z; Bs[kq*4+3][c] = v.w;
        }
        __syncthreads();

#pragma unroll
        for (int kk = 0; kk < 16; kk++) {
            ulonglong2 b01 = *(const ulonglong2*)&Bs[kk][tx*8];
            ulonglong2 b23 = *(const ulonglong2*)&Bs[kk][tx*8+4];
            ull b2[4] = {b01.x, b01.y, b23.x, b23.y};
            float4 a0 = *(const float4*)&As[kk][ty*8];
            float4 a1 = *(const float4*)&As[kk][ty*8+4];
            ull a2[8] = {pack2(a0.x), pack2(a0.y), pack2(a0.z), pack2(a0.w),
                         pack2(a1.x), pack2(a1.y), pack2(a1.z), pack2(a1.w)};
#pragma unroll
            for (int i = 0; i < 8; i++)
#pragma unroll
                for (int j = 0; j < 4; j++)
                    ffma2(acc[i][j], a2[i], b2[j]);
        }
        __syncthreads();
    }

    // Epilogue: add bias, remap row=(b,s), col=(h,d) -> [b,h,s,d].
    const int cbase = c0 + tx * 8;          // 8 cols, never crosses a head
    const int h  = cbase / HD;
    const int d0 = cbase % HD;
    float bs[8];
#pragma unroll
    for (int j = 0; j < 8; j++) bs[j] = bias[cbase + j];

#pragma unroll
    for (int i = 0; i < 8; i++) {
        int r = r0 + ty * 8 + i;
        int b = r / SS, s = r % SS;
        float* dst = Y + (((size_t)(b * NH + h) * SS + s) * HD + d0);
        float vals[8];
#pragma unroll
        for (int j = 0; j < 4; j++) {
            float2 f = unpack2(acc[i][j]);
            vals[j*2]   = f.x + bs[j*2];
            vals[j*2+1] = f.y + bs[j*2+1];
        }
        *(float4*)dst       = *(float4*)&vals[0];
        *(float4*)(dst + 4) = *(float4*)&vals[4];
    }
}

// ---------------------------------------------------------------------------
// Kernel 2: scores = q @ k^T / 8 with key-padding mask -> raw scores into the
// w output region.  Per (b,h), tile 128(i) x 128(j), K=64 in smem (transposed,
// stride 132).  256 threads, 8x8 microtile via f32x2 (pairs along j).
// ---------------------------------------------------------------------------
#define SC_STRIDE 132
__global__ __launch_bounds__(256) void scores_kernel(
    const int* __restrict__ mask, float* __restrict__ wbuf)
{
    extern __shared__ float sm2[];
    float* QsT = sm2;                     // [64][132]
    float* KsT = sm2 + 64 * SC_STRIDE;    // [64][132]
    __shared__ int msk[128];

    const int j0 = blockIdx.x * 128;
    const int i0 = blockIdx.y * 128;
    const int z  = blockIdx.z;            // b*NH + h
    const int bidx = z / NH;
    const int t  = threadIdx.x;
    const int tx = t & 15;
    const int ty = t >> 4;

    const float* qbase = g_q + ((size_t)z * SS + i0) * HD;  // 128x64 contiguous
    const float* kbase = g_k + ((size_t)z * SS + j0) * HD;

#pragma unroll
    for (int u = 0; u < 8; u++) {
        int l = u * 256 + t;          // float4 id, 2048 total
        int i = l >> 4;               // row within tile
        int dq = l & 15;              // float4 within row
        float4 v = ((const float4*)qbase)[l];
        int d = dq * 4;
        QsT[(d+0)*SC_STRIDE + i] = v.x; QsT[(d+1)*SC_STRIDE + i] = v.y;
        QsT[(d+2)*SC_STRIDE + i] = v.z; QsT[(d+3)*SC_STRIDE + i] = v.w;
        float4 w = ((const float4*)kbase)[l];
        KsT[(d+0)*SC_STRIDE + i] = w.x; KsT[(d+1)*SC_STRIDE + i] = w.y;
        KsT[(d+2)*SC_STRIDE + i] = w.z; KsT[(d+3)*SC_STRIDE + i] = w.w;
    }
    if (t < 128) msk[t] = mask[(size_t)bidx * SS + j0 + t];
    __syncthreads();

    ull acc[8][4];
#pragma unroll
    for (int i = 0; i < 8; i++)
#pragma unroll
        for (int j = 0; j < 4; j++) acc[i][j] = 0ull;

#pragma unroll 8
    for (int d = 0; d < 64; d++) {
        ulonglong2 b01 = *(const ulonglong2*)&KsT[d*SC_STRIDE + tx*8];
        ulonglong2 b23 = *(const ulonglong2*)&KsT[d*SC_STRIDE + tx*8+4];
        ull b2[4] = {b01.x, b01.y, b23.x, b23.y};
        float4 a0 = *(const float4*)&QsT[d*SC_STRIDE + ty*8];
        float4 a1 = *(const float4*)&QsT[d*SC_STRIDE + ty*8+4];
        ull a2[8] = {pack2(a0.x), pack2(a0.y), pack2(a0.z), pack2(a0.w),
                     pack2(a1.x), pack2(a1.y), pack2(a1.z), pack2(a1.w)};
#pragma unroll
        for (int i = 0; i < 8; i++)
#pragma unroll
            for (int j = 0; j < 4; j++)
                ffma2(acc[i][j], a2[i], b2[j]);
    }

    const float NEG_INF = __int_as_float(0xff800000);
#pragma unroll
    for (int ii = 0; ii < 8; ii++) {
        int row = i0 + ty * 8 + ii;
        float* dst = wbuf + ((size_t)z * SS + row) * SS + j0 + tx * 8;
        float vals[8];
#pragma unroll
        for (int jj = 0; jj < 4; jj++) {
            float2 f = unpack2(acc[ii][jj]);
            float s0 = f.x * 0.125f;
            float s1 = f.y * 0.125f;
            vals[jj*2]   = (msk[tx*8 + jj*2]   > 0) ? NEG_INF : s0;
            vals[jj*2+1] = (msk[tx*8 + jj*2+1] > 0) ? NEG_INF : s1;
        }
        *(float4*)dst       = *(float4*)&vals[0];
        *(float4*)(dst + 4) = *(float4*)&vals[4];
    }
}

// ---------------------------------------------------------------------------
// Kernel 3: per-row softmax + hard threshold + L1 renormalize, in place.
// One block (256 threads) per row of 2048; 8 elements/thread.
// ---------------------------------------------------------------------------
__device__ __forceinline__ float warpMax(float v) {
#pragma unroll
    for (int o = 16; o; o >>= 1) v = fmaxf(v, __shfl_xor_sync(0xffffffffu, v, o));
    return v;
}
__device__ __forceinline__ float warpSum(float v) {
#pragma unroll
    for (int o = 16; o; o >>= 1) v += __shfl_xor_sync(0xffffffffu, v, o);
    return v;
}
__device__ float blockMax(float v, float* red) {
    v = warpMax(v);
    int w = threadIdx.x >> 5, lane = threadIdx.x & 31;
    if (lane == 0) red[w] = v;
    __syncthreads();
    float r = (lane < 8) ? red[lane] : __int_as_float(0xff800000);
    if (w == 0) { r = warpMax(r); if (lane == 0) red[0] = r; }
    __syncthreads();
    float out = red[0];
    __syncthreads();
    return out;
}
__device__ float blockSum(float v, float* red) {
    v = warpSum(v);
    int w = threadIdx.x >> 5, lane = threadIdx.x & 31;
    if (lane == 0) red[w] = v;
    __syncthreads();
    float r = (lane < 8) ? red[lane] : 0.0f;
    if (w == 0) { r = warpSum(r); if (lane == 0) red[0] = r; }
    __syncthreads();
    float out = red[0];
    __syncthreads();
    return out;
}

__global__ __launch_bounds__(256) void softmax_kernel(float* __restrict__ wbuf)
{
    __shared__ float red[8];
    const size_t row = blockIdx.x;
    float* p = wbuf + row * SS;
    const int t = threadIdx.x;

    float4 x0 = ((const float4*)p)[t];
    float4 x1 = ((const float4*)p)[t + 256];
    float v[8] = {x0.x, x0.y, x0.z, x0.w, x1.x, x1.y, x1.z, x1.w};

    float m = v[0];
#pragma unroll
    for (int i = 1; i < 8; i++) m = fmaxf(m, v[i]);
    m = blockMax(m, red);

    float e[8], es = 0.0f;
#pragma unroll
    for (int i = 0; i < 8; i++) { e[i] = expf(v[i] - m); es += e[i]; }
    es = blockSum(es, red);

    float w[8], l1 = 0.0f;
#pragma unroll
    for (int i = 0; i < 8; i++) {
        float wi = e[i] / es;                    // IEEE fp32 divide
        wi = (wi < 0.001f) ? 0.0f : wi;          // hard threshold
        w[i] = wi;
        l1 += wi;
    }
    l1 = blockSum(l1, red);
    float denom = fmaxf(l1, 1e-12f);

#pragma unroll
    for (int i = 0; i < 8; i++) w[i] = w[i] / denom;

    float4 o0 = make_float4(w[0], w[1], w[2], w[3]);
    float4 o1 = make_float4(w[4], w[5], w[6], w[7]);
    ((float4*)p)[t]       = o0;
    ((float4*)p)[t + 256] = o1;
}

// ---------------------------------------------------------------------------
// Kernel 4: out = w @ v per (b,h) slice, with layout transform to [B,S,H].
// BM=128 (i), BN=64 (full hd), BK=32 (j).  256 threads, 8x4 microtile via
// f32x2 with pairs along i (A pairs read free from smem; only 4 packs/step).
// ---------------------------------------------------------------------------
#define AV_STRIDE 132
__global__ __launch_bounds__(256) void av_kernel(
    const float* __restrict__ wbuf, float* __restrict__ out)
{
    __shared__ float WsT[32 * AV_STRIDE];   // [j][i]
    __shared__ float Vs[32 * 64];           // [j][d]

    const int i0 = blockIdx.x * 128;
    const int z  = blockIdx.y;              // b*NH + h
    const int bidx = z / NH;
    const int h    = z % NH;
    const int t  = threadIdx.x;
    const int tx = t & 15;
    const int ty = t >> 4;

    ull acc[4][4];   // [i-pair][j]
#pragma unroll
    for (int i = 0; i < 4; i++)
#pragma unroll
        for (int j = 0; j < 4; j++) acc[i][j] = 0ull;

    for (int j0 = 0; j0 < SS; j0 += 32) {
        // w tile 128x32 transposed
#pragma unroll
        for (int u = 0; u < 4; u++) {
            int l = u * 256 + t;      // float4 id, 1024 total
            int r = l >> 3;
            int jq = l & 7;
            float4 v = *(const float4*)(wbuf + ((size_t)z * SS + i0 + r) * SS + j0 + jq * 4);
            WsT[(jq*4+0)*AV_STRIDE + r] = v.x;
            WsT[(jq*4+1)*AV_STRIDE + r] = v.y;
            WsT[(jq*4+2)*AV_STRIDE + r] = v.z;
            WsT[(jq*4+3)*AV_STRIDE + r] = v.w;
        }
        // v tile 32x64, contiguous copy
        const float4* vsrc = (const float4*)(g_v + ((size_t)z * SS + j0) * HD);
#pragma unroll
        for (int u = 0; u < 2; u++) {
            int l = u * 256 + t;      // 512 float4
            ((float4*)Vs)[l] = vsrc[l];
        }
        __syncthreads();

#pragma unroll 8
        for (int j = 0; j < 32; j++) {
            ulonglong2 a01 = *(const ulonglong2*)&WsT[j*AV_STRIDE + ty*8];
            ulonglong2 a23 = *(const ulonglong2*)&WsT[j*AV_STRIDE + ty*8+4];
            ull a2[4] = {a01.x, a01.y, a23.x, a23.y};
            float4 bv = *(const float4*)&Vs[j*64 + tx*4];
            ull b2[4] = {pack2(bv.x), pack2(bv.y), pack2(bv.z), pack2(bv.w)};
#pragma unroll
            for (int ip = 0; ip < 4; ip++)
#pragma unroll
                for (int jj = 0; jj < 4; jj++)
                    ffma2(acc[ip][jj], a2[ip], b2[jj]);
        }
        __syncthreads();
    }

#pragma unroll
    for (int ip = 0; ip < 4; ip++) {
        float v0[4], v1[4];
#pragma unroll
        for (int jj = 0; jj < 4; jj++) {
            float2 f = unpack2(acc[ip][jj]);
            v0[jj] = f.x;
            v1[jj] = f.y;
        }
        int srow = i0 + ty * 8 + ip * 2;
        float* dst0 = out + ((size_t)bidx * SS + srow)     * HH + h * HD + tx * 4;
        float* dst1 = out + ((size_t)bidx * SS + srow + 1) * HH + h * HD + tx * 4;
        *(float4*)dst0 = *(float4*)&v0[0];
        *(float4*)dst1 = *(float4*)&v1[0];
    }
}

// ---------------------------------------------------------------------------
extern "C" void kernel_launch(void* const* d_in, const int* in_sizes, int n_in,
                              void* d_out, int out_size)
{
    const float* query = (const float*)d_in[0];
    const float* key   = (const float*)d_in[1];
    const float* value = (const float*)d_in[2];
    const int*   mask  = (const int*)  d_in[3];
    const float* Wq    = (const float*)d_in[4];
    const float* bq    = (const float*)d_in[5];
    const float* Wk    = (const float*)d_in[6];
    const float* bk    = (const float*)d_in[7];
    const float* Wv    = (const float*)d_in[8];
    const float* bv    = (const float*)d_in[9];

    float* out  = (float*)d_out;
    float* wbuf = out + (size_t)BB * SS * HH;   // w output region

    float *qp, *kp, *vp;
    cudaGetSymbolAddress((void**)&qp, g_q);
    cudaGetSymbolAddress((void**)&kp, g_k);
    cudaGetSymbolAddress((void**)&vp, g_v);

    // 1) Projections (q,k,v fused over blockIdx.z)
    dim3 gProj(HH / 128, (BB * SS) / 128, 3);   // (8, 32, 3)
    proj_kernel<<<gProj, 256>>>(query, key, value, Wq, Wk, Wv,
                                bq, bk, bv, qp, kp, vp);

    // 2) Scores (raw, masked) into w region
    size_t smScores = 2 * 64 * SC_STRIDE * sizeof(float);  // ~67.6 KB
    cudaFuncSetAttribute(scores_kernel,
                         cudaFuncAttributeMaxDynamicSharedMemorySize,
                         (int)smScores);
    dim3 gScores(SS / 128, SS / 128, BB * NH);   // (16, 16, 32)
    scores_kernel<<<gScores, 256, smScores>>>(mask, wbuf);

    // 3) Softmax + threshold + L1 renorm, in place
    softmax_kernel<<<BB * NH * SS, 256>>>(wbuf);

    // 4) out = w @ v
    dim3 gAV(SS / 128, BB * NH);   // (16, 32)
    av_kernel<<<gAV, 256>>>(wbuf, out);
}

// round 4
// speedup vs baseline: 1.0460x; 1.0460x over previous
#include <cuda_runtime.h>
#include <cstdint>

#define BB 2
#define SS 2048
#define HH 1024
#define NH 16
#define HD 64
#define QKV_ELEMS (BB*NH*SS*HD)   // 4,194,304

// Scratch: projected q, k, v in [B, heads, S, hd] layout (16 MB each).
__device__ float g_q[QKV_ELEMS];
__device__ float g_k[QKV_ELEMS];
__device__ float g_v[QKV_ELEMS];

// ---------------------------------------------------------------------------
// tf32 helpers (legacy mma.sync path; no sm_103a-only instructions).
// ---------------------------------------------------------------------------
__device__ __forceinline__ void split_tf32(float x, uint32_t& hi, uint32_t& lo) {
    uint32_t h;
    asm("cvt.rna.tf32.f32 %0, %1;" : "=r"(h) : "f"(x));
    float resid = x - __uint_as_float(h);
    uint32_t l;
    asm("cvt.rna.tf32.f32 %0, %1;" : "=r"(l) : "f"(resid));
    hi = h; lo = l;
}

#define MMA_TF32(c, a, b)                                                      \
    asm volatile("mma.sync.aligned.m16n8k8.row.col.f32.tf32.tf32.f32 "         \
        "{%0,%1,%2,%3}, {%4,%5,%6,%7}, {%8,%9}, {%0,%1,%2,%3};"                \
        : "+f"((c)[0]), "+f"((c)[1]), "+f"((c)[2]), "+f"((c)[3])               \
        : "r"((a)[0]), "r"((a)[1]), "r"((a)[2]), "r"((a)[3]),                  \
          "r"((b)[0]), "r"((b)[1]))

// ---------------------------------------------------------------------------
// Kernel 1: fused projection GEMMs (scalar fp32; numerics-critical for q,k).
// Y = X @ W^T + b, remapped to [B, heads, S, hd].  BM=BN=128, BK=16.
// ---------------------------------------------------------------------------
__global__ __launch_bounds__(256) void proj_kernel(
    const float* __restrict__ Xq, const float* __restrict__ Xk,
    const float* __restrict__ Xv,
    const float* __restrict__ Wq, const float* __restrict__ Wk,
    const float* __restrict__ Wv,
    const float* __restrict__ bq, const float* __restrict__ bk,
    const float* __restrict__ bv,
    float* __restrict__ Yq, float* __restrict__ Yk, float* __restrict__ Yv)
{
    __shared__ float As[16][128];
    __shared__ float Bs[16][128];

    const float* X; const float* W; const float* bias; float* Y;
    if (blockIdx.z == 0)      { X = Xq; W = Wq; bias = bq; Y = Yq; }
    else if (blockIdx.z == 1) { X = Xk; W = Wk; bias = bk; Y = Yk; }
    else                      { X = Xv; W = Wv; bias = bv; Y = Yv; }

    const int r0 = blockIdx.y * 128;
    const int c0 = blockIdx.x * 128;
    const int t  = threadIdx.x;
    const int tx = t & 15;
    const int ty = t >> 4;

    float acc[8][8];
#pragma unroll
    for (int i = 0; i < 8; i++)
#pragma unroll
        for (int j = 0; j < 8; j++) acc[i][j] = 0.0f;

    for (int k0 = 0; k0 < HH; k0 += 16) {
#pragma unroll
        for (int u = 0; u < 2; u++) {
            int l = u * 256 + t;
            int r = l >> 2;
            int kq = l & 3;
            float4 v = *(const float4*)(X + (size_t)(r0 + r) * HH + k0 + kq * 4);
            As[kq*4+0][r] = v.x; As[kq*4+1][r] = v.y;
            As[kq*4+2][r] = v.z; As[kq*4+3][r] = v.w;
        }
#pragma unroll
        for (int u = 0; u < 2; u++) {
            int l = u * 256 + t;
            int c = l >> 2;
            int kq = l & 3;
            float4 v = *(const float4*)(W + (size_t)(c0 + c) * HH + k0 + kq * 4);
            Bs[kq*4+0][c] = v.x; Bs[kq*4+1][c] = v.y;
            Bs[kq*4+2][c] = v.z; Bs[kq*4+3][c] = v.w;
        }
        __syncthreads();

#pragma unroll
        for (int kk = 0; kk < 16; kk++) {
            float a[8], b[8];
            *(float4*)&a[0] = *(float4*)&As[kk][ty*8];
            *(float4*)&a[4] = *(float4*)&As[kk][ty*8+4];
            *(float4*)&b[0] = *(float4*)&Bs[kk][tx*8];
            *(float4*)&b[4] = *(float4*)&Bs[kk][tx*8+4];
#pragma unroll
            for (int i = 0; i < 8; i++)
#pragma unroll
                for (int j = 0; j < 8; j++)
                    acc[i][j] += a[i] * b[j];
        }
        __syncthreads();
    }

    const int cbase = c0 + tx * 8;
    const int h  = cbase / HD;
    const int d0 = cbase % HD;
    float bs[8];
#pragma unroll
    for (int j = 0; j < 8; j++) bs[j] = bias[cbase + j];

#pragma unroll
    for (int i = 0; i < 8; i++) {
        int r = r0 + ty * 8 + i;
        int b = r / SS, s = r % SS;
        float* dst = Y + (((size_t)(b * NH + h) * SS + s) * HD + d0);
        float4 o0 = make_float4(acc[i][0]+bs[0], acc[i][1]+bs[1],
                                acc[i][2]+bs[2], acc[i][3]+bs[3]);
        float4 o1 = make_float4(acc[i][4]+bs[4], acc[i][5]+bs[5],
                                acc[i][6]+bs[6], acc[i][7]+bs[7]);
        *(float4*)dst = o0;
        *(float4*)(dst + 4) = o1;
    }
}

// ---------------------------------------------------------------------------
// Kernel 2: scores = q @ k^T / 8 + mask -> raw scores (scalar fp32, exact —
// pre-threshold, so numerics must match the fp32 reference closely).
// ---------------------------------------------------------------------------
#define SC_STRIDE 132
__global__ __launch_bounds__(256) void scores_kernel(
    const int* __restrict__ mask, float* __restrict__ wbuf)
{
    extern __shared__ float sm2[];
    float* QsT = sm2;
    float* KsT = sm2 + 64 * SC_STRIDE;
    __shared__ int msk[128];

    const int j0 = blockIdx.x * 128;
    const int i0 = blockIdx.y * 128;
    const int z  = blockIdx.z;
    const int bidx = z / NH;
    const int t  = threadIdx.x;
    const int tx = t & 15;
    const int ty = t >> 4;

    const float* qbase = g_q + ((size_t)z * SS + i0) * HD;
    const float* kbase = g_k + ((size_t)z * SS + j0) * HD;

#pragma unroll
    for (int u = 0; u < 8; u++) {
        int l = u * 256 + t;
        int i = l >> 4;
        int dq = l & 15;
        float4 v = ((const float4*)qbase)[l];
        int d = dq * 4;
        QsT[(d+0)*SC_STRIDE + i] = v.x; QsT[(d+1)*SC_STRIDE + i] = v.y;
        QsT[(d+2)*SC_STRIDE + i] = v.z; QsT[(d+3)*SC_STRIDE + i] = v.w;
        float4 w = ((const float4*)kbase)[l];
        KsT[(d+0)*SC_STRIDE + i] = w.x; KsT[(d+1)*SC_STRIDE + i] = w.y;
        KsT[(d+2)*SC_STRIDE + i] = w.z; KsT[(d+3)*SC_STRIDE + i] = w.w;
    }
    if (t < 128) msk[t] = mask[(size_t)bidx * SS + j0 + t];
    __syncthreads();

    float acc[8][8];
#pragma unroll
    for (int i = 0; i < 8; i++)
#pragma unroll
        for (int j = 0; j < 8; j++) acc[i][j] = 0.0f;

#pragma unroll 8
    for (int d = 0; d < 64; d++) {
        float a[8], b[8];
        *(float4*)&a[0] = *(float4*)&QsT[d*SC_STRIDE + ty*8];
        *(float4*)&a[4] = *(float4*)&QsT[d*SC_STRIDE + ty*8+4];
        *(float4*)&b[0] = *(float4*)&KsT[d*SC_STRIDE + tx*8];
        *(float4*)&b[4] = *(float4*)&KsT[d*SC_STRIDE + tx*8+4];
#pragma unroll
        for (int i = 0; i < 8; i++)
#pragma unroll
            for (int j = 0; j < 8; j++)
                acc[i][j] += a[i] * b[j];
    }

    const float NEG_INF = __int_as_float(0xff800000);
#pragma unroll
    for (int ii = 0; ii < 8; ii++) {
        int row = i0 + ty * 8 + ii;
        float* dst = wbuf + ((size_t)z * SS + row) * SS + j0 + tx * 8;
        float vals[8];
#pragma unroll
        for (int jj = 0; jj < 8; jj++) {
            float s = acc[ii][jj] * 0.125f;
            vals[jj] = (msk[tx*8 + jj] > 0) ? NEG_INF : s;
        }
        *(float4*)dst       = *(float4*)&vals[0];
        *(float4*)(dst + 4) = *(float4*)&vals[4];
    }
}

// ---------------------------------------------------------------------------
// Kernel 3: per-row softmax + threshold + L1 renorm (exact fp32, in place).
// ---------------------------------------------------------------------------
__device__ __forceinline__ float warpMax(float v) {
#pragma unroll
    for (int o = 16; o; o >>= 1) v = fmaxf(v, __shfl_xor_sync(0xffffffffu, v, o));
    return v;
}
__device__ __forceinline__ float warpSum(float v) {
#pragma unroll
    for (int o = 16; o; o >>= 1) v += __shfl_xor_sync(0xffffffffu, v, o);
    return v;
}
__device__ float blockMax(float v, float* red) {
    v = warpMax(v);
    int w = threadIdx.x >> 5, lane = threadIdx.x & 31;
    if (lane == 0) red[w] = v;
    __syncthreads();
    float r = (lane < 8) ? red[lane] : __int_as_float(0xff800000);
    if (w == 0) { r = warpMax(r); if (lane == 0) red[0] = r; }
    __syncthreads();
    float out = red[0];
    __syncthreads();
    return out;
}
__device__ float blockSum(float v, float* red) {
    v = warpSum(v);
    int w = threadIdx.x >> 5, lane = threadIdx.x & 31;
    if (lane == 0) red[w] = v;
    __syncthreads();
    float r = (lane < 8) ? red[lane] : 0.0f;
    if (w == 0) { r = warpSum(r); if (lane == 0) red[0] = r; }
    __syncthreads();
    float out = red[0];
    __syncthreads();
    return out;
}

__global__ __launch_bounds__(256) void softmax_kernel(float* __restrict__ wbuf)
{
    __shared__ float red[8];
    const size_t row = blockIdx.x;
    float* p = wbuf + row * SS;
    const int t = threadIdx.x;

    float4 x0 = ((const float4*)p)[t];
    float4 x1 = ((const float4*)p)[t + 256];
    float v[8] = {x0.x, x0.y, x0.z, x0.w, x1.x, x1.y, x1.z, x1.w};

    float m = v[0];
#pragma unroll
    for (int i = 1; i < 8; i++) m = fmaxf(m, v[i]);
    m = blockMax(m, red);

    float e[8], es = 0.0f;
#pragma unroll
    for (int i = 0; i < 8; i++) { e[i] = expf(v[i] - m); es += e[i]; }
    es = blockSum(es, red);

    float w[8], l1 = 0.0f;
#pragma unroll
    for (int i = 0; i < 8; i++) {
        float wi = e[i] / es;
        wi = (wi < 0.001f) ? 0.0f : wi;
        w[i] = wi;
        l1 += wi;
    }
    l1 = blockSum(l1, red);
    float denom = fmaxf(l1, 1e-12f);

#pragma unroll
    for (int i = 0; i < 8; i++) w[i] = w[i] / denom;

    float4 o0 = make_float4(w[0], w[1], w[2], w[3]);
    float4 o1 = make_float4(w[4], w[5], w[6], w[7]);
    ((float4*)p)[t]       = o0;
    ((float4*)p)[t + 256] = o1;
}

// ---------------------------------------------------------------------------
// Kernel 4: out = w @ v via legacy mma.sync 3xTF32 (error-safe: w is
// post-threshold; out perturbation ~1e-7 cannot flip anything).
// Per (b,h): D[128 i][64 d] = sum_j w[i][j] v[j][d].  BK=32, 8 warps in a
// 4(i) x 2(d) grid, warp tile 32x32 = 2 m-tiles x 4 n-tiles of m16n8k8.
// Smem holds hi/lo tf32 splits; pad strides 36 / 72 give conflict-free
// fragment loads (banks 4g+t resp. 8t+g).
// ---------------------------------------------------------------------------
#define AV_W_STRIDE 36
#define AV_V_STRIDE 72
#define AV_SMEM_U32 (2*128*AV_W_STRIDE + 2*32*AV_V_STRIDE)   // 13824 u32 = 55296 B

__global__ __launch_bounds__(256) void av_mma_kernel(
    const float* __restrict__ wbuf, float* __restrict__ out)
{
    extern __shared__ uint32_t sm[];
    uint32_t* Whi = sm;                                  // [128][36]
    uint32_t* Wlo = sm + 128*AV_W_STRIDE;
    uint32_t* Vhi = sm + 2*128*AV_W_STRIDE;              // [32][72]
    uint32_t* Vlo = Vhi + 32*AV_V_STRIDE;

    const int t    = threadIdx.x;
    const int wid  = t >> 5;
    const int lane = t & 31;
    const int gq   = lane >> 2;     // 0..7
    const int tq   = lane & 3;      // 0..3
    const int wi   = wid >> 1;      // 0..3 (i)
    const int wd   = wid & 1;       // 0..1 (d)

    const int i0 = blockIdx.x * 128;
    const int z  = blockIdx.y;
    const int bidx = z / NH;
    const int h    = z % NH;

    const float* Wbase = wbuf + (size_t)z * SS * SS + (size_t)i0 * SS;
    const float* Vbase = g_v + (size_t)z * SS * HD;

    float acc[2][4][4];
#pragma unroll
    for (int mt = 0; mt < 2; mt++)
#pragma unroll
        for (int nt = 0; nt < 4; nt++)
#pragma unroll
            for (int r = 0; r < 4; r++) acc[mt][nt][r] = 0.0f;

    for (int c = 0; c < SS / 32; c++) {
        const int j0 = c * 32;

        // Load + split w tile [128 i][32 j]
#pragma unroll
        for (int u = 0; u < 4; u++) {
            int g = u * 256 + t;
            int r = g >> 3, cq = g & 7;
            float4 v = *(const float4*)(Wbase + (size_t)r * SS + j0 + cq * 4);
            uint32_t h0,l0,h1,l1,h2,l2,h3,l3;
            split_tf32(v.x, h0, l0); split_tf32(v.y, h1, l1);
            split_tf32(v.z, h2, l2); split_tf32(v.w, h3, l3);
            int idx = r * AV_W_STRIDE + cq * 4;
            *(uint4*)&Whi[idx] = make_uint4(h0, h1, h2, h3);
            *(uint4*)&Wlo[idx] = make_uint4(l0, l1, l2, l3);
        }
        // Load + split v tile [32 j][64 d]
#pragma unroll
        for (int u = 0; u < 2; u++) {
            int g = u * 256 + t;
            int r = g >> 4, cq = g & 15;
            float4 v = *(const float4*)(Vbase + (size_t)(j0 + r) * HD + cq * 4);
            uint32_t h0,l0,h1,l1,h2,l2,h3,l3;
            split_tf32(v.x, h0, l0); split_tf32(v.y, h1, l1);
            split_tf32(v.z, h2, l2); split_tf32(v.w, h3, l3);
            int idx = r * AV_V_STRIDE + cq * 4;
            *(uint4*)&Vhi[idx] = make_uint4(h0, h1, h2, h3);
            *(uint4*)&Vlo[idx] = make_uint4(l0, l1, l2, l3);
        }
        __syncthreads();

#pragma unroll
        for (int ks = 0; ks < 4; ks++) {
            const int kk = ks * 8;

            uint32_t ah[2][4], al[2][4];
#pragma unroll
            for (int mt = 0; mt < 2; mt++) {
                int m = wi * 32 + mt * 16 + gq;
                int base = m * AV_W_STRIDE + kk + tq;
                ah[mt][0] = Whi[base];
                ah[mt][1] = Whi[base + 8*AV_W_STRIDE];
                ah[mt][2] = Whi[base + 4];
                ah[mt][3] = Whi[base + 8*AV_W_STRIDE + 4];
                al[mt][0] = Wlo[base];
                al[mt][1] = Wlo[base + 8*AV_W_STRIDE];
                al[mt][2] = Wlo[base + 4];
                al[mt][3] = Wlo[base + 8*AV_W_STRIDE + 4];
            }
            uint32_t bh[4][2], bl[4][2];
#pragma unroll
            for (int nt = 0; nt < 4; nt++) {
                int n = wd * 32 + nt * 8 + gq;
                int base = (kk + tq) * AV_V_STRIDE + n;
                bh[nt][0] = Vhi[base];
                bh[nt][1] = Vhi[base + 4*AV_V_STRIDE];
                bl[nt][0] = Vlo[base];
                bl[nt][1] = Vlo[base + 4*AV_V_STRIDE];
            }
#pragma unroll
            for (int mt = 0; mt < 2; mt++)
#pragma unroll
                for (int nt = 0; nt < 4; nt++) {
                    MMA_TF32(acc[mt][nt], ah[mt], bh[nt]);
                    MMA_TF32(acc[mt][nt], ah[mt], bl[nt]);
                    MMA_TF32(acc[mt][nt], al[mt], bh[nt]);
                }
        }
        __syncthreads();
    }

    // Epilogue: c0=[g][2t], c1=[g][2t+1], c2=[g+8][2t], c3=[g+8][2t+1]
#pragma unroll
    for (int mt = 0; mt < 2; mt++) {
        int row = i0 + wi * 32 + mt * 16 + gq;
#pragma unroll
        for (int nt = 0; nt < 4; nt++) {
            int col = h * HD + wd * 32 + nt * 8 + 2 * tq;
            float* d0 = out + ((size_t)bidx * SS + row) * HH + col;
            float* d1 = out + ((size_t)bidx * SS + row + 8) * HH + col;
            *(float2*)d0 = make_float2(acc[mt][nt][0], acc[mt][nt][1]);
            *(float2*)d1 = make_float2(acc[mt][nt][2], acc[mt][nt][3]);
        }
    }
}

// ---------------------------------------------------------------------------
extern "C" void kernel_launch(void* const* d_in, const int* in_sizes, int n_in,
                              void* d_out, int out_size)
{
    const float* query = (const float*)d_in[0];
    const float* key   = (const float*)d_in[1];
    const float* value = (const float*)d_in[2];
    const int*   mask  = (const int*)  d_in[3];
    const float* Wq    = (const float*)d_in[4];
    const float* bq    = (const float*)d_in[5];
    const float* Wk    = (const float*)d_in[6];
    const float* bk    = (const float*)d_in[7];
    const float* Wv    = (const float*)d_in[8];
    const float* bv    = (const float*)d_in[9];

    float* out  = (float*)d_out;
    float* wbuf = out + (size_t)BB * SS * HH;

    float *qp, *kp, *vp;
    cudaGetSymbolAddress((void**)&qp, g_q);
    cudaGetSymbolAddress((void**)&kp, g_k);
    cudaGetSymbolAddress((void**)&vp, g_v);

    // 1) Projections (q,k,v fused over blockIdx.z)
    dim3 gProj(HH / 128, (BB * SS) / 128, 3);
    proj_kernel<<<gProj, 256>>>(query, key, value, Wq, Wk, Wv,
                                bq, bk, bv, qp, kp, vp);

    // 2) Scores (raw, masked) into w region
    size_t smScores = 2 * 64 * SC_STRIDE * sizeof(float);
    cudaFuncSetAttribute(scores_kernel,
                         cudaFuncAttributeMaxDynamicSharedMemorySize,
                         (int)smScores);
    dim3 gScores(SS / 128, SS / 128, BB * NH);
    scores_kernel<<<gScores, 256, smScores>>>(mask, wbuf);

    // 3) Softmax + threshold + L1 renorm, in place
    softmax_kernel<<<BB * NH * SS, 256>>>(wbuf);

    // 4) out = w @ v on legacy tensor path (mma.sync 3xTF32)
    size_t smAV = AV_SMEM_U32 * sizeof(uint32_t);   // 55296 B
    cudaFuncSetAttribute(av_mma_kernel,
                         cudaFuncAttributeMaxDynamicSharedMemorySize,
                         (int)smAV);
    dim3 gAV(SS / 128, BB * NH);
    av_mma_kernel<<<gAV, 256, smAV>>>(wbuf, out);
}

// round 5
// speedup vs baseline: 1.3190x; 1.2610x over previous
#include <cuda_runtime.h>
#include <cstdint>

#define BB 2
#define SS 2048
#define HH 1024
#define NH 16
#define HD 64
#define QKV_ELEMS (BB*NH*SS*HD)   // 4,194,304

// Scratch: projected q, k, v in [B, heads, S, hd]; v packed fp16 pairs.
__device__ float    g_q[QKV_ELEMS];
__device__ float    g_k[QKV_ELEMS];
__device__ float    g_v[QKV_ELEMS];
__device__ uint32_t g_vp[QKV_ELEMS / 2];   // [z][s/2][d] half2(v[2s2][d], v[2s2+1][d])

// ---------------------------------------------------------------------------
// Precision helpers
// ---------------------------------------------------------------------------
__device__ __forceinline__ void split_tf32(float x, uint32_t& hi, uint32_t& lo) {
    uint32_t h;
    asm("cvt.rna.tf32.f32 %0, %1;" : "=r"(h) : "f"(x));
    float resid = x - __uint_as_float(h);
    uint32_t l;
    asm("cvt.rna.tf32.f32 %0, %1;" : "=r"(l) : "f"(resid));
    hi = h; lo = l;
}
__device__ __forceinline__ uint32_t f16x2(float lo, float hi) {
    uint32_t r;
    asm("cvt.rn.f16x2.f32 %0, %1, %2;" : "=r"(r) : "f"(hi), "f"(lo));
    return r;
}

#define MMA_TF32(c, a, b)                                                      \
    asm volatile("mma.sync.aligned.m16n8k8.row.col.f32.tf32.tf32.f32 "         \
        "{%0,%1,%2,%3}, {%4,%5,%6,%7}, {%8,%9}, {%0,%1,%2,%3};"                \
        : "+f"((c)[0]), "+f"((c)[1]), "+f"((c)[2]), "+f"((c)[3])               \
        : "r"((a)[0]), "r"((a)[1]), "r"((a)[2]), "r"((a)[3]),                  \
          "r"((b)[0]), "r"((b)[1]))

#define MMA_F16(c, a, b)                                                       \
    asm volatile("mma.sync.aligned.m16n8k16.row.col.f32.f16.f16.f32 "          \
        "{%0,%1,%2,%3}, {%4,%5,%6,%7}, {%8,%9}, {%0,%1,%2,%3};"                \
        : "+f"((c)[0]), "+f"((c)[1]), "+f"((c)[2]), "+f"((c)[3])               \
        : "r"((a)[0]), "r"((a)[1]), "r"((a)[2]), "r"((a)[3]),                  \
          "r"((b)[0]), "r"((b)[1]))

// ---------------------------------------------------------------------------
// Kernel 1: fused projection GEMMs (scalar fp32; q/k numerics-critical).
// ---------------------------------------------------------------------------
__global__ __launch_bounds__(256) void proj_kernel(
    const float* __restrict__ Xq, const float* __restrict__ Xk,
    const float* __restrict__ Xv,
    const float* __restrict__ Wq, const float* __restrict__ Wk,
    const float* __restrict__ Wv,
    const float* __restrict__ bq, const float* __restrict__ bk,
    const float* __restrict__ bv,
    float* __restrict__ Yq, float* __restrict__ Yk, float* __restrict__ Yv)
{
    __shared__ float As[16][128];
    __shared__ float Bs[16][128];

    const float* X; const float* W; const float* bias; float* Y;
    if (blockIdx.z == 0)      { X = Xq; W = Wq; bias = bq; Y = Yq; }
    else if (blockIdx.z == 1) { X = Xk; W = Wk; bias = bk; Y = Yk; }
    else                      { X = Xv; W = Wv; bias = bv; Y = Yv; }

    const int r0 = blockIdx.y * 128;
    const int c0 = blockIdx.x * 128;
    const int t  = threadIdx.x;
    const int tx = t & 15;
    const int ty = t >> 4;

    float acc[8][8];
#pragma unroll
    for (int i = 0; i < 8; i++)
#pragma unroll
        for (int j = 0; j < 8; j++) acc[i][j] = 0.0f;

    for (int k0 = 0; k0 < HH; k0 += 16) {
#pragma unroll
        for (int u = 0; u < 2; u++) {
            int l = u * 256 + t;
            int r = l >> 2;
            int kq = l & 3;
            float4 v = *(const float4*)(X + (size_t)(r0 + r) * HH + k0 + kq * 4);
            As[kq*4+0][r] = v.x; As[kq*4+1][r] = v.y;
            As[kq*4+2][r] = v.z; As[kq*4+3][r] = v.w;
        }
#pragma unroll
        for (int u = 0; u < 2; u++) {
            int l = u * 256 + t;
            int c = l >> 2;
            int kq = l & 3;
            float4 v = *(const float4*)(W + (size_t)(c0 + c) * HH + k0 + kq * 4);
            Bs[kq*4+0][c] = v.x; Bs[kq*4+1][c] = v.y;
            Bs[kq*4+2][c] = v.z; Bs[kq*4+3][c] = v.w;
        }
        __syncthreads();

#pragma unroll
        for (int kk = 0; kk < 16; kk++) {
            float a[8], b[8];
            *(float4*)&a[0] = *(float4*)&As[kk][ty*8];
            *(float4*)&a[4] = *(float4*)&As[kk][ty*8+4];
            *(float4*)&b[0] = *(float4*)&Bs[kk][tx*8];
            *(float4*)&b[4] = *(float4*)&Bs[kk][tx*8+4];
#pragma unroll
            for (int i = 0; i < 8; i++)
#pragma unroll
                for (int j = 0; j < 8; j++)
                    acc[i][j] += a[i] * b[j];
        }
        __syncthreads();
    }

    const int cbase = c0 + tx * 8;
    const int h  = cbase / HD;
    const int d0 = cbase % HD;
    float bs[8];
#pragma unroll
    for (int j = 0; j < 8; j++) bs[j] = bias[cbase + j];

#pragma unroll
    for (int i = 0; i < 8; i++) {
        int r = r0 + ty * 8 + i;
        int b = r / SS, s = r % SS;
        float* dst = Y + (((size_t)(b * NH + h) * SS + s) * HD + d0);
        float4 o0 = make_float4(acc[i][0]+bs[0], acc[i][1]+bs[1],
                                acc[i][2]+bs[2], acc[i][3]+bs[3]);
        float4 o1 = make_float4(acc[i][4]+bs[4], acc[i][5]+bs[5],
                                acc[i][6]+bs[6], acc[i][7]+bs[7]);
        *(float4*)dst = o0;
        *(float4*)(dst + 4) = o1;
    }
}

// ---------------------------------------------------------------------------
// Kernel 1b: pack v into fp16 pairs along s:  g_vp[s2][d] = (v[2s2][d], v[2s2+1][d])
// ---------------------------------------------------------------------------
__global__ __launch_bounds__(256) void pack_v_kernel()
{
    int u = blockIdx.x * 256 + threadIdx.x;   // uint4 id, 524288 total
    int s2row = u >> 4;                       // z*1024 + s2
    int cq = u & 15;
    const float* p = g_v + (size_t)s2row * 128 + cq * 4;
    float4 a = *(const float4*)p;             // row 2*s2   (k even -> lo)
    float4 b = *(const float4*)(p + 64);      // row 2*s2+1 (k odd  -> hi)
    uint4 o = make_uint4(f16x2(a.x, b.x), f16x2(a.y, b.y),
                         f16x2(a.z, b.z), f16x2(a.w, b.w));
    *(uint4*)(g_vp + (size_t)s2row * 64 + cq * 4) = o;
}

// ---------------------------------------------------------------------------
// Kernel 2: scores = q @ k^T / 8 + mask via mma.sync 3xTF32.
// Block: 128(i) x 64(j), K=64 fully in smem (natural [row][68] layout, no
// transpose: B-fragment elements are Ks[n][k] addresses).  8 warps 4x2,
// warp tile 32x32, split-on-register-load.
// ---------------------------------------------------------------------------
#define SQ_STR 68
#define SC_SMEM_BYTES (192 * SQ_STR * 4 + 64 * 4)

__global__ __launch_bounds__(256) void scores_mma_kernel(
    const int* __restrict__ mask, float* __restrict__ wbuf)
{
    extern __shared__ float smem[];
    float* Qs = smem;                    // [128][68]
    float* Ks = smem + 128 * SQ_STR;     // [64][68]
    int*   msk = (int*)(smem + 192 * SQ_STR);

    const int j0 = blockIdx.x * 64;
    const int i0 = blockIdx.y * 128;
    const int z  = blockIdx.z;
    const int bidx = z / NH;
    const int t    = threadIdx.x;
    const int wid  = t >> 5;
    const int lane = t & 31;
    const int gq   = lane >> 2;
    const int tq   = lane & 3;
    const int wi   = wid >> 1;           // 0..3 (i)
    const int wd   = wid & 1;            // 0..1 (j)

    const float* qbase = g_q + ((size_t)z * SS + i0) * HD;
    const float* kbase = g_k + ((size_t)z * SS + j0) * HD;

#pragma unroll
    for (int u = 0; u < 8; u++) {
        int l = u * 256 + t;
        int r = l >> 4, cq = l & 15;
        float4 v = ((const float4*)qbase)[l];
        *(float4*)&Qs[r * SQ_STR + cq * 4] = v;
    }
#pragma unroll
    for (int u = 0; u < 4; u++) {
        int l = u * 256 + t;
        int r = l >> 4, cq = l & 15;
        float4 v = ((const float4*)kbase)[l];
        *(float4*)&Ks[r * SQ_STR + cq * 4] = v;
    }
    if (t < 64) msk[t] = mask[(size_t)bidx * SS + j0 + t];
    __syncthreads();

    float acc[2][4][4];
#pragma unroll
    for (int mt = 0; mt < 2; mt++)
#pragma unroll
        for (int nt = 0; nt < 4; nt++)
#pragma unroll
            for (int r = 0; r < 4; r++) acc[mt][nt][r] = 0.0f;

#pragma unroll
    for (int ks = 0; ks < 8; ks++) {
        const int kk = ks * 8;

        uint32_t ah[2][4], al[2][4];
#pragma unroll
        for (int mt = 0; mt < 2; mt++) {
            int m = wi * 32 + mt * 16 + gq;
            float x0 = Qs[m * SQ_STR + kk + tq];
            float x1 = Qs[(m + 8) * SQ_STR + kk + tq];
            float x2 = Qs[m * SQ_STR + kk + tq + 4];
            float x3 = Qs[(m + 8) * SQ_STR + kk + tq + 4];
            split_tf32(x0, ah[mt][0], al[mt][0]);
            split_tf32(x1, ah[mt][1], al[mt][1]);
            split_tf32(x2, ah[mt][2], al[mt][2]);
            split_tf32(x3, ah[mt][3], al[mt][3]);
        }
        uint32_t bh[4][2], bl[4][2];
#pragma unroll
        for (int nt = 0; nt < 4; nt++) {
            int n = wd * 32 + nt * 8 + gq;
            float y0 = Ks[n * SQ_STR + kk + tq];
            float y1 = Ks[n * SQ_STR + kk + tq + 4];
            split_tf32(y0, bh[nt][0], bl[nt][0]);
            split_tf32(y1, bh[nt][1], bl[nt][1]);
        }
#pragma unroll
        for (int mt = 0; mt < 2; mt++)
#pragma unroll
            for (int nt = 0; nt < 4; nt++) {
                MMA_TF32(acc[mt][nt], ah[mt], bh[nt]);
                MMA_TF32(acc[mt][nt], ah[mt], bl[nt]);
                MMA_TF32(acc[mt][nt], al[mt], bh[nt]);
            }
    }

    const float NEG_INF = __int_as_float(0xff800000);
#pragma unroll
    for (int mt = 0; mt < 2; mt++) {
        int r = i0 + wi * 32 + mt * 16 + gq;
#pragma unroll
        for (int nt = 0; nt < 4; nt++) {
            int jl = wd * 32 + nt * 8 + 2 * tq;
            int m0 = msk[jl], m1 = msk[jl + 1];
            float v0 = (m0 > 0) ? NEG_INF : acc[mt][nt][0] * 0.125f;
            float v1 = (m1 > 0) ? NEG_INF : acc[mt][nt][1] * 0.125f;
            float v2 = (m0 > 0) ? NEG_INF : acc[mt][nt][2] * 0.125f;
            float v3 = (m1 > 0) ? NEG_INF : acc[mt][nt][3] * 0.125f;
            float* d0 = wbuf + ((size_t)z * SS + r) * SS + j0 + jl;
            float* d1 = wbuf + ((size_t)z * SS + r + 8) * SS + j0 + jl;
            *(float2*)d0 = make_float2(v0, v1);
            *(float2*)d1 = make_float2(v2, v3);
        }
    }
}

// ---------------------------------------------------------------------------
// Kernel 3: per-row softmax + threshold + L1 renorm (exact fp32, unchanged).
// ---------------------------------------------------------------------------
__device__ __forceinline__ float warpMax(float v) {
#pragma unroll
    for (int o = 16; o; o >>= 1) v = fmaxf(v, __shfl_xor_sync(0xffffffffu, v, o));
    return v;
}
__device__ __forceinline__ float warpSum(float v) {
#pragma unroll
    for (int o = 16; o; o >>= 1) v += __shfl_xor_sync(0xffffffffu, v, o);
    return v;
}
__device__ float blockMax(float v, float* red) {
    v = warpMax(v);
    int w = threadIdx.x >> 5, lane = threadIdx.x & 31;
    if (lane == 0) red[w] = v;
    __syncthreads();
    float r = (lane < 8) ? red[lane] : __int_as_float(0xff800000);
    if (w == 0) { r = warpMax(r); if (lane == 0) red[0] = r; }
    __syncthreads();
    float out = red[0];
    __syncthreads();
    return out;
}
__device__ float blockSum(float v, float* red) {
    v = warpSum(v);
    int w = threadIdx.x >> 5, lane = threadIdx.x & 31;
    if (lane == 0) red[w] = v;
    __syncthreads();
    float r = (lane < 8) ? red[lane] : 0.0f;
    if (w == 0) { r = warpSum(r); if (lane == 0) red[0] = r; }
    __syncthreads();
    float out = red[0];
    __syncthreads();
    return out;
}

__global__ __launch_bounds__(256) void softmax_kernel(float* __restrict__ wbuf)
{
    __shared__ float red[8];
    const size_t row = blockIdx.x;
    float* p = wbuf + row * SS;
    const int t = threadIdx.x;

    float4 x0 = ((const float4*)p)[t];
    float4 x1 = ((const float4*)p)[t + 256];
    float v[8] = {x0.x, x0.y, x0.z, x0.w, x1.x, x1.y, x1.z, x1.w};

    float m = v[0];
#pragma unroll
    for (int i = 1; i < 8; i++) m = fmaxf(m, v[i]);
    m = blockMax(m, red);

    float e[8], es = 0.0f;
#pragma unroll
    for (int i = 0; i < 8; i++) { e[i] = expf(v[i] - m); es += e[i]; }
    es = blockSum(es, red);

    float w[8], l1 = 0.0f;
#pragma unroll
    for (int i = 0; i < 8; i++) {
        float wi = e[i] / es;
        wi = (wi < 0.001f) ? 0.0f : wi;
        w[i] = wi;
        l1 += wi;
    }
    l1 = blockSum(l1, red);
    float denom = fmaxf(l1, 1e-12f);

#pragma unroll
    for (int i = 0; i < 8; i++) w[i] = w[i] / denom;

    float4 o0 = make_float4(w[0], w[1], w[2], w[3]);
    float4 o1 = make_float4(w[4], w[5], w[6], w[7]);
    ((float4*)p)[t]       = o0;
    ((float4*)p)[t + 256] = o1;
}

// ---------------------------------------------------------------------------
// Kernel 4: out = w @ v via fp16 mma.sync m16n8k16 (post-threshold, fp16
// quantization of w,v adds ~1e-5 abs to out — far inside budget).
// BM=128, BN=64(full hd), BK=32.  8 warps 4x2, warp tile 32x32.
// ---------------------------------------------------------------------------
#define AVW_STR 18
#define AVV_STR 72

__global__ __launch_bounds__(256) void av_f16_kernel(
    const float* __restrict__ wbuf, float* __restrict__ out)
{
    __shared__ uint32_t Wh[128 * AVW_STR];   // half2 pairs along k
    __shared__ uint32_t Vp[16 * AVV_STR];    // half2 pairs along k

    const int t    = threadIdx.x;
    const int wid  = t >> 5;
    const int lane = t & 31;
    const int gq   = lane >> 2;
    const int tq   = lane & 3;
    const int wi   = wid >> 1;
    const int wd   = wid & 1;

    const int i0 = blockIdx.x * 128;
    const int z  = blockIdx.y;
    const int bidx = z / NH;
    const int h    = z % NH;

    const float*    Wbase  = wbuf + (size_t)z * SS * SS + (size_t)i0 * SS;
    const uint32_t* Vpbase = g_vp + (size_t)z * (SS / 2) * HD;

    float acc[2][4][4];
#pragma unroll
    for (int mt = 0; mt < 2; mt++)
#pragma unroll
        for (int nt = 0; nt < 4; nt++)
#pragma unroll
            for (int r = 0; r < 4; r++) acc[mt][nt][r] = 0.0f;

    for (int c = 0; c < SS / 32; c++) {
        const int j0 = c * 32;

        // w tile 128x32 -> fp16 pairs
#pragma unroll
        for (int u = 0; u < 4; u++) {
            int l = u * 256 + t;
            int r = l >> 3, cq = l & 7;
            float4 v = *(const float4*)(Wbase + (size_t)r * SS + j0 + cq * 4);
            Wh[r * AVW_STR + cq * 2]     = f16x2(v.x, v.y);
            Wh[r * AVW_STR + cq * 2 + 1] = f16x2(v.z, v.w);
        }
        // v packed tile: 16 packed rows x 64
        {
            int r = t >> 4, cq = t & 15;
            uint4 pv = *(const uint4*)(Vpbase + (size_t)(j0 / 2 + r) * HD + cq * 4);
            *(uint4*)&Vp[r * AVV_STR + cq * 4] = pv;
        }
        __syncthreads();

#pragma unroll
        for (int ks = 0; ks < 2; ks++) {
            uint32_t a[2][4];
#pragma unroll
            for (int mt = 0; mt < 2; mt++) {
                int m = wi * 32 + mt * 16 + gq;
                a[mt][0] = Wh[m * AVW_STR + ks * 8 + tq];
                a[mt][1] = Wh[(m + 8) * AVW_STR + ks * 8 + tq];
                a[mt][2] = Wh[m * AVW_STR + ks * 8 + tq + 4];
                a[mt][3] = Wh[(m + 8) * AVW_STR + ks * 8 + tq + 4];
            }
            uint32_t b[4][2];
#pragma unroll
            for (int nt = 0; nt < 4; nt++) {
                int n = wd * 32 + nt * 8 + gq;
                b[nt][0] = Vp[(ks * 8 + tq) * AVV_STR + n];
                b[nt][1] = Vp[(ks * 8 + tq + 4) * AVV_STR + n];
            }
#pragma unroll
            for (int mt = 0; mt < 2; mt++)
#pragma unroll
                for (int nt = 0; nt < 4; nt++)
                    MMA_F16(acc[mt][nt], a[mt], b[nt]);
        }
        __syncthreads();
    }

#pragma unroll
    for (int mt = 0; mt < 2; mt++) {
        int row = i0 + wi * 32 + mt * 16 + gq;
#pragma unroll
        for (int nt = 0; nt < 4; nt++) {
            int col = h * HD + wd * 32 + nt * 8 + 2 * tq;
            float* d0 = out + ((size_t)bidx * SS + row) * HH + col;
            float* d1 = out + ((size_t)bidx * SS + row + 8) * HH + col;
            *(float2*)d0 = make_float2(acc[mt][nt][0], acc[mt][nt][1]);
            *(float2*)d1 = make_float2(acc[mt][nt][2], acc[mt][nt][3]);
        }
    }
}

// ---------------------------------------------------------------------------
extern "C" void kernel_launch(void* const* d_in, const int* in_sizes, int n_in,
                              void* d_out, int out_size)
{
    const float* query = (const float*)d_in[0];
    const float* key   = (const float*)d_in[1];
    const float* value = (const float*)d_in[2];
    const int*   mask  = (const int*)  d_in[3];
    const float* Wq    = (const float*)d_in[4];
    const float* bq    = (const float*)d_in[5];
    const float* Wk    = (const float*)d_in[6];
    const float* bk    = (const float*)d_in[7];
    const float* Wv    = (const float*)d_in[8];
    const float* bv    = (const float*)d_in[9];

    float* out  = (float*)d_out;
    float* wbuf = out + (size_t)BB * SS * HH;

    float *qp, *kp, *vp;
    cudaGetSymbolAddress((void**)&qp, g_q);
    cudaGetSymbolAddress((void**)&kp, g_k);
    cudaGetSymbolAddress((void**)&vp, g_v);

    // 1) Projections (q,k,v fused over blockIdx.z)
    dim3 gProj(HH / 128, (BB * SS) / 128, 3);
    proj_kernel<<<gProj, 256>>>(query, key, value, Wq, Wk, Wv,
                                bq, bk, bv, qp, kp, vp);

    // 1b) pack v -> fp16 pairs
    pack_v_kernel<<<(QKV_ELEMS / 8) / 256, 256>>>();

    // 2) Scores via 3xTF32 mma.sync
    cudaFuncSetAttribute(scores_mma_kernel,
                         cudaFuncAttributeMaxDynamicSharedMemorySize,
                         SC_SMEM_BYTES);
    dim3 gScores(SS / 64, SS / 128, BB * NH);   // (32, 16, 32)
    scores_mma_kernel<<<gScores, 256, SC_SMEM_BYTES>>>(mask, wbuf);

    // 3) Softmax + threshold + L1 renorm, in place (bit-identical)
    softmax_kernel<<<BB * NH * SS, 256>>>(wbuf);

    // 4) out = w @ v via fp16 mma.sync
    dim3 gAV(SS / 128, BB * NH);
    av_f16_kernel<<<gAV, 256>>>(wbuf, out);
}

// round 7
// speedup vs baseline: 1.6381x; 1.2419x over previous
#include <cuda_runtime.h>
#include <cstdint>

#define BB 2
#define SS 2048
#define HH 1024
#define NH 16
#define HD 64
#define QKV_ELEMS (BB*NH*SS*HD)   // 4,194,304

// Scratch: projected q, k, v in [B, heads, S, hd]; v packed fp16 pairs.
__device__ float    g_q[QKV_ELEMS];
__device__ float    g_k[QKV_ELEMS];
__device__ float    g_v[QKV_ELEMS];
__device__ uint32_t g_vp[QKV_ELEMS / 2];   // [z][s/2][d] half2(v[2s2][d], v[2s2+1][d])

// ---------------------------------------------------------------------------
// Precision helpers
// ---------------------------------------------------------------------------
__device__ __forceinline__ void split_tf32(float x, uint32_t& hi, uint32_t& lo) {
    uint32_t h;
    asm("cvt.rna.tf32.f32 %0, %1;" : "=r"(h) : "f"(x));
    float resid = x - __uint_as_float(h);
    uint32_t l;
    asm("cvt.rna.tf32.f32 %0, %1;" : "=r"(l) : "f"(resid));
    hi = h; lo = l;
}
__device__ __forceinline__ uint32_t f16x2(float lo, float hi) {
    uint32_t r;
    asm("cvt.rn.f16x2.f32 %0, %1, %2;" : "=r"(r) : "f"(hi), "f"(lo));
    return r;
}

#define MMA_TF32(c, a, b)                                                      \
    asm volatile("mma.sync.aligned.m16n8k8.row.col.f32.tf32.tf32.f32 "         \
        "{%0,%1,%2,%3}, {%4,%5,%6,%7}, {%8,%9}, {%0,%1,%2,%3};"                \
        : "+f"((c)[0]), "+f"((c)[1]), "+f"((c)[2]), "+f"((c)[3])               \
        : "r"((a)[0]), "r"((a)[1]), "r"((a)[2]), "r"((a)[3]),                  \
          "r"((b)[0]), "r"((b)[1]))

#define MMA_F16(c, a, b)                                                       \
    asm volatile("mma.sync.aligned.m16n8k16.row.col.f32.f16.f16.f32 "          \
        "{%0,%1,%2,%3}, {%4,%5,%6,%7}, {%8,%9}, {%0,%1,%2,%3};"                \
        : "+f"((c)[0]), "+f"((c)[1]), "+f"((c)[2]), "+f"((c)[3])               \
        : "r"((a)[0]), "r"((a)[1]), "r"((a)[2]), "r"((a)[3]),                  \
          "r"((b)[0]), "r"((b)[1]))

// ---------------------------------------------------------------------------
// Kernel 1a: q/k projection GEMMs, scalar fp32 (numerics-critical: errors
// here flip threshold decisions; 3xTF32 measured 4x over budget at K=1024).
// ---------------------------------------------------------------------------
__global__ __launch_bounds__(256) void proj_kernel(
    const float* __restrict__ Xq, const float* __restrict__ Xk,
    const float* __restrict__ Wq, const float* __restrict__ Wk,
    const float* __restrict__ bq, const float* __restrict__ bk,
    float* __restrict__ Yq, float* __restrict__ Yk)
{
    __shared__ float As[16][128];
    __shared__ float Bs[16][128];

    const float* X; const float* W; const float* bias; float* Y;
    if (blockIdx.z == 0) { X = Xq; W = Wq; bias = bq; Y = Yq; }
    else                 { X = Xk; W = Wk; bias = bk; Y = Yk; }

    const int r0 = blockIdx.y * 128;
    const int c0 = blockIdx.x * 128;
    const int t  = threadIdx.x;
    const int tx = t & 15;
    const int ty = t >> 4;

    float acc[8][8];
#pragma unroll
    for (int i = 0; i < 8; i++)
#pragma unroll
        for (int j = 0; j < 8; j++) acc[i][j] = 0.0f;

    for (int k0 = 0; k0 < HH; k0 += 16) {
#pragma unroll
        for (int u = 0; u < 2; u++) {
            int l = u * 256 + t;
            int r = l >> 2;
            int kq = l & 3;
            float4 v = *(const float4*)(X + (size_t)(r0 + r) * HH + k0 + kq * 4);
            As[kq*4+0][r] = v.x; As[kq*4+1][r] = v.y;
            As[kq*4+2][r] = v.z; As[kq*4+3][r] = v.w;
        }
#pragma unroll
        for (int u = 0; u < 2; u++) {
            int l = u * 256 + t;
            int c = l >> 2;
            int kq = l & 3;
            float4 v = *(const float4*)(W + (size_t)(c0 + c) * HH + k0 + kq * 4);
            Bs[kq*4+0][c] = v.x; Bs[kq*4+1][c] = v.y;
            Bs[kq*4+2][c] = v.z; Bs[kq*4+3][c] = v.w;
        }
        __syncthreads();

#pragma unroll
        for (int kk = 0; kk < 16; kk++) {
            float a[8], b[8];
            *(float4*)&a[0] = *(float4*)&As[kk][ty*8];
            *(float4*)&a[4] = *(float4*)&As[kk][ty*8+4];
            *(float4*)&b[0] = *(float4*)&Bs[kk][tx*8];
            *(float4*)&b[4] = *(float4*)&Bs[kk][tx*8+4];
#pragma unroll
            for (int i = 0; i < 8; i++)
#pragma unroll
                for (int j = 0; j < 8; j++)
                    acc[i][j] += a[i] * b[j];
        }
        __syncthreads();
    }

    const int cbase = c0 + tx * 8;
    const int h  = cbase / HD;
    const int d0 = cbase % HD;
    float bs[8];
#pragma unroll
    for (int j = 0; j < 8; j++) bs[j] = bias[cbase + j];

#pragma unroll
    for (int i = 0; i < 8; i++) {
        int r = r0 + ty * 8 + i;
        int b = r / SS, s = r % SS;
        float* dst = Y + (((size_t)(b * NH + h) * SS + s) * HD + d0);
        float4 o0 = make_float4(acc[i][0]+bs[0], acc[i][1]+bs[1],
                                acc[i][2]+bs[2], acc[i][3]+bs[3]);
        float4 o1 = make_float4(acc[i][4]+bs[4], acc[i][5]+bs[5],
                                acc[i][6]+bs[6], acc[i][7]+bs[7]);
        *(float4*)dst = o0;
        *(float4*)(dst + 4) = o1;
    }
}

// ---------------------------------------------------------------------------
// Kernel 1b: v projection via mma.sync 3xTF32 (error-safe: v only reaches
// `out` through the fp16 av path where fp16 quantization dominates; w is
// untouched).  128(m) x 64(n), BK=32, 8 warps 4x2.
// ---------------------------------------------------------------------------
#define PJ_STR 36
__global__ __launch_bounds__(256) void projv_mma_kernel(
    const float* __restrict__ X, const float* __restrict__ W,
    const float* __restrict__ bias, float* __restrict__ Y)
{
    __shared__ float As[128 * PJ_STR];
    __shared__ float Bs[64 * PJ_STR];

    const int c0 = blockIdx.x * 64;
    const int r0 = blockIdx.y * 128;
    const int t    = threadIdx.x;
    const int wid  = t >> 5;
    const int lane = t & 31;
    const int gq   = lane >> 2;
    const int tq   = lane & 3;
    const int wi   = wid >> 1;
    const int wd   = wid & 1;

    float acc[2][4][4];
#pragma unroll
    for (int mt = 0; mt < 2; mt++)
#pragma unroll
        for (int nt = 0; nt < 4; nt++)
#pragma unroll
            for (int r = 0; r < 4; r++) acc[mt][nt][r] = 0.0f;

    for (int k0 = 0; k0 < HH; k0 += 32) {
#pragma unroll
        for (int u = 0; u < 4; u++) {
            int l = u * 256 + t;
            int r = l >> 3, cq = l & 7;
            float4 v = *(const float4*)(X + (size_t)(r0 + r) * HH + k0 + cq * 4);
            *(float4*)&As[r * PJ_STR + cq * 4] = v;
        }
#pragma unroll
        for (int u = 0; u < 2; u++) {
            int l = u * 256 + t;
            int r = l >> 3, cq = l & 7;
            float4 v = *(const float4*)(W + (size_t)(c0 + r) * HH + k0 + cq * 4);
            *(float4*)&Bs[r * PJ_STR + cq * 4] = v;
        }
        __syncthreads();

#pragma unroll
        for (int ks = 0; ks < 4; ks++) {
            const int kk = ks * 8;

            uint32_t ah[2][4], al[2][4];
#pragma unroll
            for (int mt = 0; mt < 2; mt++) {
                int m = wi * 32 + mt * 16 + gq;
                split_tf32(As[m * PJ_STR + kk + tq],           ah[mt][0], al[mt][0]);
                split_tf32(As[(m + 8) * PJ_STR + kk + tq],     ah[mt][1], al[mt][1]);
                split_tf32(As[m * PJ_STR + kk + tq + 4],       ah[mt][2], al[mt][2]);
                split_tf32(As[(m + 8) * PJ_STR + kk + tq + 4], ah[mt][3], al[mt][3]);
            }
            uint32_t bh[4][2], bl[4][2];
#pragma unroll
            for (int nt = 0; nt < 4; nt++) {
                int n = wd * 32 + nt * 8 + gq;
                split_tf32(Bs[n * PJ_STR + kk + tq],     bh[nt][0], bl[nt][0]);
                split_tf32(Bs[n * PJ_STR + kk + tq + 4], bh[nt][1], bl[nt][1]);
            }
#pragma unroll
            for (int mt = 0; mt < 2; mt++)
#pragma unroll
                for (int nt = 0; nt < 4; nt++) {
                    MMA_TF32(acc[mt][nt], ah[mt], bh[nt]);
                    MMA_TF32(acc[mt][nt], ah[mt], bl[nt]);
                    MMA_TF32(acc[mt][nt], al[mt], bh[nt]);
                }
        }
        __syncthreads();
    }

    const int h = c0 / HD;
#pragma unroll
    for (int mt = 0; mt < 2; mt++) {
        int row = r0 + wi * 32 + mt * 16 + gq;
        int b = row / SS, s = row % SS;
#pragma unroll
        for (int nt = 0; nt < 4; nt++) {
            int dl = wd * 32 + nt * 8 + 2 * tq;
            float bs0 = bias[c0 + dl];
            float bs1 = bias[c0 + dl + 1];
            float* d0 = Y + (((size_t)(b * NH + h) * SS + s) * HD + dl);
            float* d1 = Y + (((size_t)(b * NH + h) * SS + s + 8) * HD + dl);
            *(float2*)d0 = make_float2(acc[mt][nt][0] + bs0, acc[mt][nt][1] + bs1);
            *(float2*)d1 = make_float2(acc[mt][nt][2] + bs0, acc[mt][nt][3] + bs1);
        }
    }
}

// ---------------------------------------------------------------------------
// Kernel 1c: pack v into fp16 pairs along s.
// ---------------------------------------------------------------------------
__global__ __launch_bounds__(256) void pack_v_kernel()
{
    int u = blockIdx.x * 256 + threadIdx.x;   // uint4 id, 524288 total
    int s2row = u >> 4;                       // z*1024 + s2
    int cq = u & 15;
    const float* p = g_v + (size_t)s2row * 128 + cq * 4;
    float4 a = *(const float4*)p;             // row 2*s2   (k even -> lo)
    float4 b = *(const float4*)(p + 64);      // row 2*s2+1 (k odd  -> hi)
    uint4 o = make_uint4(f16x2(a.x, b.x), f16x2(a.y, b.y),
                         f16x2(a.z, b.z), f16x2(a.w, b.w));
    *(uint4*)(g_vp + (size_t)s2row * 64 + cq * 4) = o;
}

// ---------------------------------------------------------------------------
// Kernel 2: scores = q @ k^T / 8 + mask via mma.sync 3xTF32 (validated R5).
// ---------------------------------------------------------------------------
#define SQ_STR 68
#define SC_SMEM_BYTES (192 * SQ_STR * 4 + 64 * 4)

__global__ __launch_bounds__(256) void scores_mma_kernel(
    const int* __restrict__ mask, float* __restrict__ wbuf)
{
    extern __shared__ float smem[];
    float* Qs = smem;                    // [128][68]
    float* Ks = smem + 128 * SQ_STR;     // [64][68]
    int*   msk = (int*)(smem + 192 * SQ_STR);

    const int j0 = blockIdx.x * 64;
    const int i0 = blockIdx.y * 128;
    const int z  = blockIdx.z;
    const int bidx = z / NH;
    const int t    = threadIdx.x;
    const int wid  = t >> 5;
    const int lane = t & 31;
    const int gq   = lane >> 2;
    const int tq   = lane & 3;
    const int wi   = wid >> 1;
    const int wd   = wid & 1;

    const float* qbase = g_q + ((size_t)z * SS + i0) * HD;
    const float* kbase = g_k + ((size_t)z * SS + j0) * HD;

#pragma unroll
    for (int u = 0; u < 8; u++) {
        int l = u * 256 + t;
        int r = l >> 4, cq = l & 15;
        float4 v = ((const float4*)qbase)[l];
        *(float4*)&Qs[r * SQ_STR + cq * 4] = v;
    }
#pragma unroll
    for (int u = 0; u < 4; u++) {
        int l = u * 256 + t;
        int r = l >> 4, cq = l & 15;
        float4 v = ((const float4*)kbase)[l];
        *(float4*)&Ks[r * SQ_STR + cq * 4] = v;
    }
    if (t < 64) msk[t] = mask[(size_t)bidx * SS + j0 + t];
    __syncthreads();

    float acc[2][4][4];
#pragma unroll
    for (int mt = 0; mt < 2; mt++)
#pragma unroll
        for (int nt = 0; nt < 4; nt++)
#pragma unroll
            for (int r = 0; r < 4; r++) acc[mt][nt][r] = 0.0f;

#pragma unroll
    for (int ks = 0; ks < 8; ks++) {
        const int kk = ks * 8;

        uint32_t ah[2][4], al[2][4];
#pragma unroll
        for (int mt = 0; mt < 2; mt++) {
            int m = wi * 32 + mt * 16 + gq;
            split_tf32(Qs[m * SQ_STR + kk + tq],           ah[mt][0], al[mt][0]);
            split_tf32(Qs[(m + 8) * SQ_STR + kk + tq],     ah[mt][1], al[mt][1]);
            split_tf32(Qs[m * SQ_STR + kk + tq + 4],       ah[mt][2], al[mt][2]);
            split_tf32(Qs[(m + 8) * SQ_STR + kk + tq + 4], ah[mt][3], al[mt][3]);
        }
        uint32_t bh[4][2], bl[4][2];
#pragma unroll
        for (int nt = 0; nt < 4; nt++) {
            int n = wd * 32 + nt * 8 + gq;
            split_tf32(Ks[n * SQ_STR + kk + tq],     bh[nt][0], bl[nt][0]);
            split_tf32(Ks[n * SQ_STR + kk + tq + 4], bh[nt][1], bl[nt][1]);
        }
#pragma unroll
        for (int mt = 0; mt < 2; mt++)
#pragma unroll
            for (int nt = 0; nt < 4; nt++) {
                MMA_TF32(acc[mt][nt], ah[mt], bh[nt]);
                MMA_TF32(acc[mt][nt], ah[mt], bl[nt]);
                MMA_TF32(acc[mt][nt], al[mt], bh[nt]);
            }
    }

    const float NEG_INF = __int_as_float(0xff800000);
#pragma unroll
    for (int mt = 0; mt < 2; mt++) {
        int r = i0 + wi * 32 + mt * 16 + gq;
#pragma unroll
        for (int nt = 0; nt < 4; nt++) {
            int jl = wd * 32 + nt * 8 + 2 * tq;
            int m0 = msk[jl], m1 = msk[jl + 1];
            float v0 = (m0 > 0) ? NEG_INF : acc[mt][nt][0] * 0.125f;
            float v1 = (m1 > 0) ? NEG_INF : acc[mt][nt][1] * 0.125f;
            float v2 = (m0 > 0) ? NEG_INF : acc[mt][nt][2] * 0.125f;
            float v3 = (m1 > 0) ? NEG_INF : acc[mt][nt][3] * 0.125f;
            float* d0 = wbuf + ((size_t)z * SS + r) * SS + j0 + jl;
            float* d1 = wbuf + ((size_t)z * SS + r + 8) * SS + j0 + jl;
            *(float2*)d0 = make_float2(v0, v1);
            *(float2*)d1 = make_float2(v2, v3);
        }
    }
}

// ---------------------------------------------------------------------------
// Kernel 3: softmax + threshold + L1 renorm, divide-free hot path.
// Threshold decision: fl(e/es) < 1e-3  <=>  e < fl(1e-3*es) except within
// ~1.2e-10 of the boundary (expected flips over all 67M elements: ~0.01).
// Surviving w = e * (1/es): <=1 ulp vs reference, output-value level only.
// ---------------------------------------------------------------------------
__device__ __forceinline__ float warpMax(float v) {
#pragma unroll
    for (int o = 16; o; o >>= 1) v = fmaxf(v, __shfl_xor_sync(0xffffffffu, v, o));
    return v;
}
__device__ __forceinline__ float warpSum(float v) {
#pragma unroll
    for (int o = 16; o; o >>= 1) v += __shfl_xor_sync(0xffffffffu, v, o);
    return v;
}
__device__ float blockMax(float v, float* red) {
    v = warpMax(v);
    int w = threadIdx.x >> 5, lane = threadIdx.x & 31;
    if (lane == 0) red[w] = v;
    __syncthreads();
    float r = (lane < 8) ? red[lane] : __int_as_float(0xff800000);
    if (w == 0) { r = warpMax(r); if (lane == 0) red[0] = r; }
    __syncthreads();
    float out = red[0];
    __syncthreads();
    return out;
}
__device__ float blockSum(float v, float* red) {
    v = warpSum(v);
    int w = threadIdx.x >> 5, lane = threadIdx.x & 31;
    if (lane == 0) red[w] = v;
    __syncthreads();
    float r = (lane < 8) ? red[lane] : 0.0f;
    if (w == 0) { r = warpSum(r); if (lane == 0) red[0] = r; }
    __syncthreads();
    float out = red[0];
    __syncthreads();
    return out;
}

__global__ __launch_bounds__(256) void softmax_kernel(float* __restrict__ wbuf)
{
    __shared__ float red[8];
    const size_t row = blockIdx.x;
    float* p = wbuf + row * SS;
    const int t = threadIdx.x;

    float4 x0 = ((const float4*)p)[t];
    float4 x1 = ((const float4*)p)[t + 256];
    float v[8] = {x0.x, x0.y, x0.z, x0.w, x1.x, x1.y, x1.z, x1.w};

    float m = v[0];
#pragma unroll
    for (int i = 1; i < 8; i++) m = fmaxf(m, v[i]);
    m = blockMax(m, red);

    float e[8], es = 0.0f;
#pragma unroll
    for (int i = 0; i < 8; i++) { e[i] = expf(v[i] - m); es += e[i]; }
    es = blockSum(es, red);

    const float tes = 0.001f * es;       // threshold in e-space
    const float inv_es = 1.0f / es;      // one divide

    float w[8], l1 = 0.0f;
#pragma unroll
    for (int i = 0; i < 8; i++) {
        float wi = (e[i] < tes) ? 0.0f : e[i] * inv_es;
        w[i] = wi;
        l1 += wi;
    }
    l1 = blockSum(l1, red);
    float rinv = 1.0f / fmaxf(l1, 1e-12f);   // one divide

#pragma unroll
    for (int i = 0; i < 8; i++) w[i] *= rinv;

    float4 o0 = make_float4(w[0], w[1], w[2], w[3]);
    float4 o1 = make_float4(w[4], w[5], w[6], w[7]);
    ((float4*)p)[t]       = o0;
    ((float4*)p)[t + 256] = o1;
}

// ---------------------------------------------------------------------------
// Kernel 4: out = w @ v via fp16 mma.sync m16n8k16 (post-threshold).
// ---------------------------------------------------------------------------
#define AVW_STR 18
#define AVV_STR 72

__global__ __launch_bounds__(256) void av_f16_kernel(
    const float* __restrict__ wbuf, float* __restrict__ out)
{
    __shared__ uint32_t Wh[128 * AVW_STR];
    __shared__ uint32_t Vp[16 * AVV_STR];

    const int t    = threadIdx.x;
    const int wid  = t >> 5;
    const int lane = t & 31;
    const int gq   = lane >> 2;
    const int tq   = lane & 3;
    const int wi   = wid >> 1;
    const int wd   = wid & 1;

    const int i0 = blockIdx.x * 128;
    const int z  = blockIdx.y;
    const int bidx = z / NH;
    const int h    = z % NH;

    const float*    Wbase  = wbuf + (size_t)z * SS * SS + (size_t)i0 * SS;
    const uint32_t* Vpbase = g_vp + (size_t)z * (SS / 2) * HD;

    float acc[2][4][4];
#pragma unroll
    for (int mt = 0; mt < 2; mt++)
#pragma unroll
        for (int nt = 0; nt < 4; nt++)
#pragma unroll
            for (int r = 0; r < 4; r++) acc[mt][nt][r] = 0.0f;

    for (int c = 0; c < SS / 32; c++) {
        const int j0 = c * 32;

#pragma unroll
        for (int u = 0; u < 4; u++) {
            int l = u * 256 + t;
            int r = l >> 3, cq = l & 7;
            float4 v = *(const float4*)(Wbase + (size_t)r * SS + j0 + cq * 4);
            Wh[r * AVW_STR + cq * 2]     = f16x2(v.x, v.y);
            Wh[r * AVW_STR + cq * 2 + 1] = f16x2(v.z, v.w);
        }
        {
            int r = t >> 4, cq = t & 15;
            uint4 pv = *(const uint4*)(Vpbase + (size_t)(j0 / 2 + r) * HD + cq * 4);
            *(uint4*)&Vp[r * AVV_STR + cq * 4] = pv;
        }
        __syncthreads();

#pragma unroll
        for (int ks = 0; ks < 2; ks++) {
            uint32_t a[2][4];
#pragma unroll
            for (int mt = 0; mt < 2; mt++) {
                int m = wi * 32 + mt * 16 + gq;
                a[mt][0] = Wh[m * AVW_STR + ks * 8 + tq];
                a[mt][1] = Wh[(m + 8) * AVW_STR + ks * 8 + tq];
                a[mt][2] = Wh[m * AVW_STR + ks * 8 + tq + 4];
                a[mt][3] = Wh[(m + 8) * AVW_STR + ks * 8 + tq + 4];
            }
            uint32_t b[4][2];
#pragma unroll
            for (int nt = 0; nt < 4; nt++) {
                int n = wd * 32 + nt * 8 + gq;
                b[nt][0] = Vp[(ks * 8 + tq) * AVV_STR + n];
                b[nt][1] = Vp[(ks * 8 + tq + 4) * AVV_STR + n];
            }
#pragma unroll
            for (int mt = 0; mt < 2; mt++)
#pragma unroll
                for (int nt = 0; nt < 4; nt++)
                    MMA_F16(acc[mt][nt], a[mt], b[nt]);
        }
        __syncthreads();
    }

#pragma unroll
    for (int mt = 0; mt < 2; mt++) {
        int row = i0 + wi * 32 + mt * 16 + gq;
#pragma unroll
        for (int nt = 0; nt < 4; nt++) {
            int col = h * HD + wd * 32 + nt * 8 + 2 * tq;
            float* d0 = out + ((size_t)bidx * SS + row) * HH + col;
            float* d1 = out + ((size_t)bidx * SS + row + 8) * HH + col;
            *(float2*)d0 = make_float2(acc[mt][nt][0], acc[mt][nt][1]);
            *(float2*)d1 = make_float2(acc[mt][nt][2], acc[mt][nt][3]);
        }
    }
}

// ---------------------------------------------------------------------------
extern "C" void kernel_launch(void* const* d_in, const int* in_sizes, int n_in,
                              void* d_out, int out_size)
{
    const float* query = (const float*)d_in[0];
    const float* key   = (const float*)d_in[1];
    const float* value = (const float*)d_in[2];
    const int*   mask  = (const int*)  d_in[3];
    const float* Wq    = (const float*)d_in[4];
    const float* bq    = (const float*)d_in[5];
    const float* Wk    = (const float*)d_in[6];
    const float* bk    = (const float*)d_in[7];
    const float* Wv    = (const float*)d_in[8];
    const float* bv    = (const float*)d_in[9];

    float* out  = (float*)d_out;
    float* wbuf = out + (size_t)BB * SS * HH;

    float *qp, *kp, *vp;
    cudaGetSymbolAddress((void**)&qp, g_q);
    cudaGetSymbolAddress((void**)&kp, g_k);
    cudaGetSymbolAddress((void**)&vp, g_v);

    // 1a) q/k projections, exact scalar fp32
    dim3 gProj(HH / 128, (BB * SS) / 128, 2);   // (8, 32, 2)
    proj_kernel<<<gProj, 256>>>(query, key, Wq, Wk, bq, bk, qp, kp);

    // 1b) v projection via 3xTF32 (error-safe)
    dim3 gProjV(HH / 64, (BB * SS) / 128);      // (16, 32)
    projv_mma_kernel<<<gProjV, 256>>>(value, Wv, bv, vp);

    // 1c) pack v -> fp16 pairs
    pack_v_kernel<<<(QKV_ELEMS / 8) / 256, 256>>>();

    // 2) Scores via 3xTF32 mma.sync
    cudaFuncSetAttribute(scores_mma_kernel,
                         cudaFuncAttributeMaxDynamicSharedMemorySize,
                         SC_SMEM_BYTES);
    dim3 gScores(SS / 64, SS / 128, BB * NH);   // (32, 16, 32)
    scores_mma_kernel<<<gScores, 256, SC_SMEM_BYTES>>>(mask, wbuf);

    // 3) Softmax + threshold + L1 renorm, divide-free hot path
    softmax_kernel<<<BB * NH * SS, 256>>>(wbuf);

    // 4) out = w @ v via fp16 mma.sync
    dim3 gAV(SS / 128, BB * NH);
    av_f16_kernel<<<gAV, 256>>>(wbuf, out);
}

// round 9
// speedup vs baseline: 1.7324x; 1.0575x over previous
#include <cuda_runtime.h>
#include <cuda_bf16.h>
#include <cstdint>

#define BB 2
#define SS 2048
#define HH 1024
#define NH 16
#define HD 64
#define QKV_ELEMS (BB*NH*SS*HD)   // 4,194,304
#define XROWS (BB*SS)             // 4096
#define KP (HH/2)                 // 512 bf16 pairs per row

// Scratch.
__device__ float    g_q[QKV_ELEMS];
__device__ float    g_k[QKV_ELEMS];
__device__ float    g_v[QKV_ELEMS];
__device__ uint32_t g_vp[QKV_ELEMS / 2];       // fp16 pairs of v along s
__device__ uint32_t g_xs[2][3][XROWS * KP];    // split query,key inputs
__device__ uint32_t g_ws[2][3][HH * KP];       // split Wq, Wk

// ---------------------------------------------------------------------------
// Precision helpers
// ---------------------------------------------------------------------------
// Lossless 3-way bf16 split of an fp32 pair: x = b1 + b2 + b3 exactly.
__device__ __forceinline__ void bsplit2(float x0, float x1,
                                        uint32_t& p1, uint32_t& p2, uint32_t& p3)
{
    __nv_bfloat162 t1 = __floats2bfloat162_rn(x0, x1);
    uint32_t u1; memcpy(&u1, &t1, 4);
    float a0 = __uint_as_float(u1 << 16);
    float a1 = __uint_as_float(u1 & 0xffff0000u);
    float r0 = x0 - a0, r1 = x1 - a1;
    __nv_bfloat162 t2 = __floats2bfloat162_rn(r0, r1);
    uint32_t u2; memcpy(&u2, &t2, 4);
    float b0 = __uint_as_float(u2 << 16);
    float b1 = __uint_as_float(u2 & 0xffff0000u);
    __nv_bfloat162 t3 = __floats2bfloat162_rn(r0 - b0, r1 - b1);
    uint32_t u3; memcpy(&u3, &t3, 4);
    p1 = u1; p2 = u2; p3 = u3;
}

__device__ __forceinline__ void split_tf32(float x, uint32_t& hi, uint32_t& lo) {
    uint32_t h;
    asm("cvt.rna.tf32.f32 %0, %1;" : "=r"(h) : "f"(x));
    float resid = x - __uint_as_float(h);
    uint32_t l;
    asm("cvt.rna.tf32.f32 %0, %1;" : "=r"(l) : "f"(resid));
    hi = h; lo = l;
}
__device__ __forceinline__ uint32_t f16x2(float lo, float hi) {
    uint32_t r;
    asm("cvt.rn.f16x2.f32 %0, %1, %2;" : "=r"(r) : "f"(hi), "f"(lo));
    return r;
}

#define MMA_BF16(c, a, b)                                                      \
    asm volatile("mma.sync.aligned.m16n8k16.row.col.f32.bf16.bf16.f32 "        \
        "{%0,%1,%2,%3}, {%4,%5,%6,%7}, {%8,%9}, {%0,%1,%2,%3};"                \
        : "+f"((c)[0]), "+f"((c)[1]), "+f"((c)[2]), "+f"((c)[3])               \
        : "r"((a)[0]), "r"((a)[1]), "r"((a)[2]), "r"((a)[3]),                  \
          "r"((b)[0]), "r"((b)[1]))

#define MMA_TF32(c, a, b)                                                      \
    asm volatile("mma.sync.aligned.m16n8k8.row.col.f32.tf32.tf32.f32 "         \
        "{%0,%1,%2,%3}, {%4,%5,%6,%7}, {%8,%9}, {%0,%1,%2,%3};"                \
        : "+f"((c)[0]), "+f"((c)[1]), "+f"((c)[2]), "+f"((c)[3])               \
        : "r"((a)[0]), "r"((a)[1]), "r"((a)[2]), "r"((a)[3]),                  \
          "r"((b)[0]), "r"((b)[1]))

#define MMA_F16(c, a, b)                                                       \
    asm volatile("mma.sync.aligned.m16n8k16.row.col.f32.f16.f16.f32 "          \
        "{%0,%1,%2,%3}, {%4,%5,%6,%7}, {%8,%9}, {%0,%1,%2,%3};"                \
        : "+f"((c)[0]), "+f"((c)[1]), "+f"((c)[2]), "+f"((c)[3])               \
        : "r"((a)[0]), "r"((a)[1]), "r"((a)[2]), "r"((a)[3]),                  \
          "r"((b)[0]), "r"((b)[1]))

// 6-term exact-bf16 product chain, SMALLEST TERMS FIRST so the biased
// per-MMA accumulator rounding acts on tiny magnitudes; only the final
// b1*b1 add rounds on chunk magnitude.
#define MMA6_REV(acc, a, b) do {                                               \
    MMA_BF16(acc, (a)[2], (b)[0]);                                             \
    MMA_BF16(acc, (a)[0], (b)[2]);                                             \
    MMA_BF16(acc, (a)[1], (b)[1]);                                             \
    MMA_BF16(acc, (a)[1], (b)[0]);                                             \
    MMA_BF16(acc, (a)[0], (b)[1]);                                             \
    MMA_BF16(acc, (a)[0], (b)[0]);                                             \
} while (0)

// ---------------------------------------------------------------------------
// Kernel 0: split an fp32 matrix into 3 packed-bf16 arrays (pairs along k).
// ---------------------------------------------------------------------------
__global__ __launch_bounds__(256) void split3_kernel(
    const float* __restrict__ src, uint32_t* __restrict__ d1,
    uint32_t* __restrict__ d2, uint32_t* __restrict__ d3, int npairs)
{
    int i = blockIdx.x * 256 + threadIdx.x;
    if (i >= npairs) return;
    float2 x = ((const float2*)src)[i];
    uint32_t p1, p2, p3;
    bsplit2(x.x, x.y, p1, p2, p3);
    d1[i] = p1; d2[i] = p2; d3[i] = p3;
}

// ---------------------------------------------------------------------------
// Kernel 1: q/k projection via 6xBF16 with PER-CHUNK accumulators.
// Each K=16 chunk goes into a fresh zero accumulator (6 chained MMAs,
// small terms first), then folds into the running fp32 total with RN adds.
// This bounds the biased tensor-core rounding to ~2e-7 relative (vs ~3e-6
// for a 384-long chain, which failed).  128(m) x 64(n), BK=32, 8 warps 4x2.
// ---------------------------------------------------------------------------
#define PJ6_STR 20
__global__ __launch_bounds__(256) void proj6_kernel(
    const float* __restrict__ bq, const float* __restrict__ bk)
{
    __shared__ uint32_t Asp[3][128 * PJ6_STR];
    __shared__ uint32_t Bsp[3][64 * PJ6_STR];

    const int zi = blockIdx.z;                 // 0=q, 1=k
    const float* bias = zi ? bk : bq;
    const uint32_t* Xb = &g_xs[zi][0][0];
    const uint32_t* Wb = &g_ws[zi][0][0];
    float* Y = zi ? g_k : g_q;

    const int c0 = blockIdx.x * 64;            // head h = blockIdx.x
    const int r0 = blockIdx.y * 128;
    const int t    = threadIdx.x;
    const int wid  = t >> 5;
    const int lane = t & 31;
    const int gq   = lane >> 2;
    const int tq   = lane & 3;
    const int wi   = wid >> 1;
    const int wd   = wid & 1;

    float acc[2][4][4];
#pragma unroll
    for (int mt = 0; mt < 2; mt++)
#pragma unroll
        for (int nt = 0; nt < 4; nt++)
#pragma unroll
            for (int r = 0; r < 4; r++) acc[mt][nt][r] = 0.0f;

    for (int c = 0; c < KP / 16; c++) {        // 32 iters of 16 pairs (32 k)
#pragma unroll
        for (int l = 0; l < 3; l++) {
            const uint32_t* Xl = Xb + (size_t)l * XROWS * KP;
            const uint32_t* Wl = Wb + (size_t)l * HH * KP;
#pragma unroll
            for (int u = 0; u < 2; u++) {
                int g = u * 256 + t;           // 512 uint4 over 128x16
                int r = g >> 2, pq = g & 3;
                uint4 v = *(const uint4*)(Xl + (size_t)(r0 + r) * KP + c * 16 + pq * 4);
                *(uint4*)&Asp[l][r * PJ6_STR + pq * 4] = v;
            }
            {
                int r = t >> 2, pq = t & 3;    // 256 uint4 over 64x16
                uint4 v = *(const uint4*)(Wl + (size_t)(c0 + r) * KP + c * 16 + pq * 4);
                *(uint4*)&Bsp[l][r * PJ6_STR + pq * 4] = v;
            }
        }
        __syncthreads();

#pragma unroll
        for (int ks = 0; ks < 2; ks++) {       // two K=16 chunks
            const int kp = ks * 8;
            uint32_t a[3][2][4], b[3][4][2];
#pragma unroll
            for (int l = 0; l < 3; l++) {
#pragma unroll
                for (int mt = 0; mt < 2; mt++) {
                    int m = wi * 32 + mt * 16 + gq;
                    a[l][mt][0] = Asp[l][m * PJ6_STR + kp + tq];
                    a[l][mt][1] = Asp[l][(m + 8) * PJ6_STR + kp + tq];
                    a[l][mt][2] = Asp[l][m * PJ6_STR + kp + tq + 4];
                    a[l][mt][3] = Asp[l][(m + 8) * PJ6_STR + kp + tq + 4];
                }
#pragma unroll
                for (int nt = 0; nt < 4; nt++) {
                    int n = wd * 32 + nt * 8 + gq;
                    b[l][nt][0] = Bsp[l][n * PJ6_STR + kp + tq];
                    b[l][nt][1] = Bsp[l][n * PJ6_STR + kp + tq + 4];
                }
            }
#pragma unroll
            for (int mt = 0; mt < 2; mt++)
#pragma unroll
                for (int nt = 0; nt < 4; nt++) {
                    uint32_t am[3][4] = {{a[0][mt][0],a[0][mt][1],a[0][mt][2],a[0][mt][3]},
                                         {a[1][mt][0],a[1][mt][1],a[1][mt][2],a[1][mt][3]},
                                         {a[2][mt][0],a[2][mt][1],a[2][mt][2],a[2][mt][3]}};
                    uint32_t bn[3][2] = {{b[0][nt][0],b[0][nt][1]},
                                         {b[1][nt][0],b[1][nt][1]},
                                         {b[2][nt][0],b[2][nt][1]}};
                    float cacc[4] = {0.0f, 0.0f, 0.0f, 0.0f};
                    MMA6_REV(cacc, am, bn);
#pragma unroll
                    for (int r = 0; r < 4; r++) acc[mt][nt][r] += cacc[r];
                }
        }
        __syncthreads();
    }

    // Epilogue: bias + write fp32 q/k in [b,h,s,d] layout.
    const int h = blockIdx.x;
#pragma unroll
    for (int mt = 0; mt < 2; mt++) {
        int row = r0 + wi * 32 + mt * 16 + gq;
        int bidx = row / SS, s = row % SS;
#pragma unroll
        for (int nt = 0; nt < 4; nt++) {
            int dl = wd * 32 + nt * 8 + 2 * tq;
            float bs0 = bias[c0 + dl], bs1 = bias[c0 + dl + 1];
            float* d0 = Y + (((size_t)(bidx * NH + h) * SS + s) * HD + dl);
            float* d1 = Y + (((size_t)(bidx * NH + h) * SS + s + 8) * HD + dl);
            *(float2*)d0 = make_float2(acc[mt][nt][0] + bs0, acc[mt][nt][1] + bs1);
            *(float2*)d1 = make_float2(acc[mt][nt][2] + bs0, acc[mt][nt][3] + bs1);
        }
    }
}

// ---------------------------------------------------------------------------
// Kernel 1b: v projection via mma.sync 3xTF32 (error-safe, validated R7).
// ---------------------------------------------------------------------------
#define PJ_STR 36
__global__ __launch_bounds__(256) void projv_mma_kernel(
    const float* __restrict__ X, const float* __restrict__ W,
    const float* __restrict__ bias, float* __restrict__ Y)
{
    __shared__ float As[128 * PJ_STR];
    __shared__ float Bs[64 * PJ_STR];

    const int c0 = blockIdx.x * 64;
    const int r0 = blockIdx.y * 128;
    const int t    = threadIdx.x;
    const int wid  = t >> 5;
    const int lane = t & 31;
    const int gq   = lane >> 2;
    const int tq   = lane & 3;
    const int wi   = wid >> 1;
    const int wd   = wid & 1;

    float acc[2][4][4];
#pragma unroll
    for (int mt = 0; mt < 2; mt++)
#pragma unroll
        for (int nt = 0; nt < 4; nt++)
#pragma unroll
            for (int r = 0; r < 4; r++) acc[mt][nt][r] = 0.0f;

    for (int k0 = 0; k0 < HH; k0 += 32) {
#pragma unroll
        for (int u = 0; u < 4; u++) {
            int l = u * 256 + t;
            int r = l >> 3, cq = l & 7;
            float4 v = *(const float4*)(X + (size_t)(r0 + r) * HH + k0 + cq * 4);
            *(float4*)&As[r * PJ_STR + cq * 4] = v;
        }
#pragma unroll
        for (int u = 0; u < 2; u++) {
            int l = u * 256 + t;
            int r = l >> 3, cq = l & 7;
            float4 v = *(const float4*)(W + (size_t)(c0 + r) * HH + k0 + cq * 4);
            *(float4*)&Bs[r * PJ_STR + cq * 4] = v;
        }
        __syncthreads();

#pragma unroll
        for (int ks = 0; ks < 4; ks++) {
            const int kk = ks * 8;

            uint32_t ah[2][4], al[2][4];
#pragma unroll
            for (int mt = 0; mt < 2; mt++) {
                int m = wi * 32 + mt * 16 + gq;
                split_tf32(As[m * PJ_STR + kk + tq],           ah[mt][0], al[mt][0]);
                split_tf32(As[(m + 8) * PJ_STR + kk + tq],     ah[mt][1], al[mt][1]);
                split_tf32(As[m * PJ_STR + kk + tq + 4],       ah[mt][2], al[mt][2]);
                split_tf32(As[(m + 8) * PJ_STR + kk + tq + 4], ah[mt][3], al[mt][3]);
            }
            uint32_t bh[4][2], bl[4][2];
#pragma unroll
            for (int nt = 0; nt < 4; nt++) {
                int n = wd * 32 + nt * 8 + gq;
                split_tf32(Bs[n * PJ_STR + kk + tq],     bh[nt][0], bl[nt][0]);
                split_tf32(Bs[n * PJ_STR + kk + tq + 4], bh[nt][1], bl[nt][1]);
            }
#pragma unroll
            for (int mt = 0; mt < 2; mt++)
#pragma unroll
                for (int nt = 0; nt < 4; nt++) {
                    MMA_TF32(acc[mt][nt], ah[mt], bh[nt]);
                    MMA_TF32(acc[mt][nt], ah[mt], bl[nt]);
                    MMA_TF32(acc[mt][nt], al[mt], bh[nt]);
                }
        }
        __syncthreads();
    }

    const int h = c0 / HD;
#pragma unroll
    for (int mt = 0; mt < 2; mt++) {
        int row = r0 + wi * 32 + mt * 16 + gq;
        int b = row / SS, s = row % SS;
#pragma unroll
        for (int nt = 0; nt < 4; nt++) {
            int dl = wd * 32 + nt * 8 + 2 * tq;
            float bs0 = bias[c0 + dl];
            float bs1 = bias[c0 + dl + 1];
            float* d0 = Y + (((size_t)(b * NH + h) * SS + s) * HD + dl);
            float* d1 = Y + (((size_t)(b * NH + h) * SS + s + 8) * HD + dl);
            *(float2*)d0 = make_float2(acc[mt][nt][0] + bs0, acc[mt][nt][1] + bs1);
            *(float2*)d1 = make_float2(acc[mt][nt][2] + bs0, acc[mt][nt][3] + bs1);
        }
    }
}

// ---------------------------------------------------------------------------
// Kernel 1c: pack v into fp16 pairs along s.
// ---------------------------------------------------------------------------
__global__ __launch_bounds__(256) void pack_v_kernel()
{
    int u = blockIdx.x * 256 + threadIdx.x;
    int s2row = u >> 4;
    int cq = u & 15;
    const float* p = g_v + (size_t)s2row * 128 + cq * 4;
    float4 a = *(const float4*)p;
    float4 b = *(const float4*)(p + 64);
    uint4 o = make_uint4(f16x2(a.x, b.x), f16x2(a.y, b.y),
                         f16x2(a.z, b.z), f16x2(a.w, b.w));
    *(uint4*)(g_vp + (size_t)s2row * 64 + cq * 4) = o;
}

// ---------------------------------------------------------------------------
// Kernel 2: scores = q @ k^T / 8 + mask via mma.sync 3xTF32 (validated R5/R7).
// ---------------------------------------------------------------------------
#define SQ_STR 68
#define SC_SMEM_BYTES (192 * SQ_STR * 4 + 64 * 4)

__global__ __launch_bounds__(256) void scores_mma_kernel(
    const int* __restrict__ mask, float* __restrict__ wbuf)
{
    extern __shared__ float smem[];
    float* Qs = smem;
    float* Ks = smem + 128 * SQ_STR;
    int*   msk = (int*)(smem + 192 * SQ_STR);

    const int j0 = blockIdx.x * 64;
    const int i0 = blockIdx.y * 128;
    const int z  = blockIdx.z;
    const int bidx = z / NH;
    const int t    = threadIdx.x;
    const int wid  = t >> 5;
    const int lane = t & 31;
    const int gq   = lane >> 2;
    const int tq   = lane & 3;
    const int wi   = wid >> 1;
    const int wd   = wid & 1;

    const float* qbase = g_q + ((size_t)z * SS + i0) * HD;
    const float* kbase = g_k + ((size_t)z * SS + j0) * HD;

#pragma unroll
    for (int u = 0; u < 8; u++) {
        int l = u * 256 + t;
        int r = l >> 4, cq = l & 15;
        float4 v = ((const float4*)qbase)[l];
        *(float4*)&Qs[r * SQ_STR + cq * 4] = v;
    }
#pragma unroll
    for (int u = 0; u < 4; u++) {
        int l = u * 256 + t;
        int r = l >> 4, cq = l & 15;
        float4 v = ((const float4*)kbase)[l];
        *(float4*)&Ks[r * SQ_STR + cq * 4] = v;
    }
    if (t < 64) msk[t] = mask[(size_t)bidx * SS + j0 + t];
    __syncthreads();

    float acc[2][4][4];
#pragma unroll
    for (int mt = 0; mt < 2; mt++)
#pragma unroll
        for (int nt = 0; nt < 4; nt++)
#pragma unroll
            for (int r = 0; r < 4; r++) acc[mt][nt][r] = 0.0f;

#pragma unroll
    for (int ks = 0; ks < 8; ks++) {
        const int kk = ks * 8;

        uint32_t ah[2][4], al[2][4];
#pragma unroll
        for (int mt = 0; mt < 2; mt++) {
            int m = wi * 32 + mt * 16 + gq;
            split_tf32(Qs[m * SQ_STR + kk + tq],           ah[mt][0], al[mt][0]);
            split_tf32(Qs[(m + 8) * SQ_STR + kk + tq],     ah[mt][1], al[mt][1]);
            split_tf32(Qs[m * SQ_STR + kk + tq + 4],       ah[mt][2], al[mt][2]);
            split_tf32(Qs[(m + 8) * SQ_STR + kk + tq + 4], ah[mt][3], al[mt][3]);
        }
        uint32_t bh[4][2], bl[4][2];
#pragma unroll
        for (int nt = 0; nt < 4; nt++) {
            int n = wd * 32 + nt * 8 + gq;
            split_tf32(Ks[n * SQ_STR + kk + tq],     bh[nt][0], bl[nt][0]);
            split_tf32(Ks[n * SQ_STR + kk + tq + 4], bh[nt][1], bl[nt][1]);
        }
#pragma unroll
        for (int mt = 0; mt < 2; mt++)
#pragma unroll
            for (int nt = 0; nt < 4; nt++) {
                MMA_TF32(acc[mt][nt], ah[mt], bh[nt]);
                MMA_TF32(acc[mt][nt], ah[mt], bl[nt]);
                MMA_TF32(acc[mt][nt], al[mt], bh[nt]);
            }
    }

    const float NEG_INF = __int_as_float(0xff800000);
#pragma unroll
    for (int mt = 0; mt < 2; mt++) {
        int r = i0 + wi * 32 + mt * 16 + gq;
#pragma unroll
        for (int nt = 0; nt < 4; nt++) {
            int jl = wd * 32 + nt * 8 + 2 * tq;
            int m0 = msk[jl], m1 = msk[jl + 1];
            float v0 = (m0 > 0) ? NEG_INF : acc[mt][nt][0] * 0.125f;
            float v1 = (m1 > 0) ? NEG_INF : acc[mt][nt][1] * 0.125f;
            float v2 = (m0 > 0) ? NEG_INF : acc[mt][nt][2] * 0.125f;
            float v3 = (m1 > 0) ? NEG_INF : acc[mt][nt][3] * 0.125f;
            float* d0 = wbuf + ((size_t)z * SS + r) * SS + j0 + jl;
            float* d1 = wbuf + ((size_t)z * SS + r + 8) * SS + j0 + jl;
            *(float2*)d0 = make_float2(v0, v1);
            *(float2*)d1 = make_float2(v2, v3);
        }
    }
}

// ---------------------------------------------------------------------------
// Kernel 3: softmax + threshold + L1 renorm (divide-free hot path, R7).
// ---------------------------------------------------------------------------
__device__ __forceinline__ float warpMax(float v) {
#pragma unroll
    for (int o = 16; o; o >>= 1) v = fmaxf(v, __shfl_xor_sync(0xffffffffu, v, o));
    return v;
}
__device__ __forceinline__ float warpSum(float v) {
#pragma unroll
    for (int o = 16; o; o >>= 1) v += __shfl_xor_sync(0xffffffffu, v, o);
    return v;
}
__device__ float blockMax(float v, float* red) {
    v = warpMax(v);
    int w = threadIdx.x >> 5, lane = threadIdx.x & 31;
    if (lane == 0) red[w] = v;
    __syncthreads();
    float r = (lane < 8) ? red[lane] : __int_as_float(0xff800000);
    if (w == 0) { r = warpMax(r); if (lane == 0) red[0] = r; }
    __syncthreads();
    float out = red[0];
    __syncthreads();
    return out;
}
__device__ float blockSum(float v, float* red) {
    v = warpSum(v);
    int w = threadIdx.x >> 5, lane = threadIdx.x & 31;
    if (lane == 0) red[w] = v;
    __syncthreads();
    float r = (lane < 8) ? red[lane] : 0.0f;
    if (w == 0) { r = warpSum(r); if (lane == 0) red[0] = r; }
    __syncthreads();
    float out = red[0];
    __syncthreads();
    return out;
}

__global__ __launch_bounds__(256) void softmax_kernel(float* __restrict__ wbuf)
{
    __shared__ float red[8];
    const size_t row = blockIdx.x;
    float* p = wbuf + row * SS;
    const int t = threadIdx.x;

    float4 x0 = ((const float4*)p)[t];
    float4 x1 = ((const float4*)p)[t + 256];
    float v[8] = {x0.x, x0.y, x0.z, x0.w, x1.x, x1.y, x1.z, x1.w};

    float m = v[0];
#pragma unroll
    for (int i = 1; i < 8; i++) m = fmaxf(m, v[i]);
    m = blockMax(m, red);

    float e[8], es = 0.0f;
#pragma unroll
    for (int i = 0; i < 8; i++) { e[i] = expf(v[i] - m); es += e[i]; }
    es = blockSum(es, red);

    const float tes = 0.001f * es;
    const float inv_es = 1.0f / es;

    float w[8], l1 = 0.0f;
#pragma unroll
    for (int i = 0; i < 8; i++) {
        float wi = (e[i] < tes) ? 0.0f : e[i] * inv_es;
        w[i] = wi;
        l1 += wi;
    }
    l1 = blockSum(l1, red);
    float rinv = 1.0f / fmaxf(l1, 1e-12f);

#pragma unroll
    for (int i = 0; i < 8; i++) w[i] *= rinv;

    float4 o0 = make_float4(w[0], w[1], w[2], w[3]);
    float4 o1 = make_float4(w[4], w[5], w[6], w[7]);
    ((float4*)p)[t]       = o0;
    ((float4*)p)[t + 256] = o1;
}

// ---------------------------------------------------------------------------
// Kernel 4: out = w @ v via fp16 mma.sync (post-threshold, R5-validated).
// ---------------------------------------------------------------------------
#define AVW_STR 18
#define AVV_STR 72

__global__ __launch_bounds__(256) void av_f16_kernel(
    const float* __restrict__ wbuf, float* __restrict__ out)
{
    __shared__ uint32_t Wh[128 * AVW_STR];
    __shared__ uint32_t Vp[16 * AVV_STR];

    const int t    = threadIdx.x;
    const int wid  = t >> 5;
    const int lane = t & 31;
    const int gq   = lane >> 2;
    const int tq   = lane & 3;
    const int wi   = wid >> 1;
    const int wd   = wid & 1;

    const int i0 = blockIdx.x * 128;
    const int z  = blockIdx.y;
    const int bidx = z / NH;
    const int h    = z % NH;

    const float*    Wbase  = wbuf + (size_t)z * SS * SS + (size_t)i0 * SS;
    const uint32_t* Vpbase = g_vp + (size_t)z * (SS / 2) * HD;

    float acc[2][4][4];
#pragma unroll
    for (int mt = 0; mt < 2; mt++)
#pragma unroll
        for (int nt = 0; nt < 4; nt++)
#pragma unroll
            for (int r = 0; r < 4; r++) acc[mt][nt][r] = 0.0f;

    for (int c = 0; c < SS / 32; c++) {
        const int j0 = c * 32;

#pragma unroll
        for (int u = 0; u < 4; u++) {
            int l = u * 256 + t;
            int r = l >> 3, cq = l & 7;
            float4 v = *(const float4*)(Wbase + (size_t)r * SS + j0 + cq * 4);
            Wh[r * AVW_STR + cq * 2]     = f16x2(v.x, v.y);
            Wh[r * AVW_STR + cq * 2 + 1] = f16x2(v.z, v.w);
        }
        {
            int r = t >> 4, cq = t & 15;
            uint4 pv = *(const uint4*)(Vpbase + (size_t)(j0 / 2 + r) * HD + cq * 4);
            *(uint4*)&Vp[r * AVV_STR + cq * 4] = pv;
        }
        __syncthreads();

#pragma unroll
        for (int ks = 0; ks < 2; ks++) {
            uint32_t a[2][4];
#pragma unroll
            for (int mt = 0; mt < 2; mt++) {
                int m = wi * 32 + mt * 16 + gq;
                a[mt][0] = Wh[m * AVW_STR + ks * 8 + tq];
                a[mt][1] = Wh[(m + 8) * AVW_STR + ks * 8 + tq];
                a[mt][2] = Wh[m * AVW_STR + ks * 8 + tq + 4];
                a[mt][3] = Wh[(m + 8) * AVW_STR + ks * 8 + tq + 4];
            }
            uint32_t b[4][2];
#pragma unroll
            for (int nt = 0; nt < 4; nt++) {
                int n = wd * 32 + nt * 8 + gq;
                b[nt][0] = Vp[(ks * 8 + tq) * AVV_STR + n];
                b[nt][1] = Vp[(ks * 8 + tq + 4) * AVV_STR + n];
            }
#pragma unroll
            for (int mt = 0; mt < 2; mt++)
#pragma unroll
                for (int nt = 0; nt < 4; nt++)
                    MMA_F16(acc[mt][nt], a[mt], b[nt]);
        }
        __syncthreads();
    }

#pragma unroll
    for (int mt = 0; mt < 2; mt++) {
        int row = i0 + wi * 32 + mt * 16 + gq;
#pragma unroll
        for (int nt = 0; nt < 4; nt++) {
            int col = h * HD + wd * 32 + nt * 8 + 2 * tq;
            float* d0 = out + ((size_t)bidx * SS + row) * HH + col;
            float* d1 = out + ((size_t)bidx * SS + row + 8) * HH + col;
            *(float2*)d0 = make_float2(acc[mt][nt][0], acc[mt][nt][1]);
            *(float2*)d1 = make_float2(acc[mt][nt][2], acc[mt][nt][3]);
        }
    }
}

// ---------------------------------------------------------------------------
extern "C" void kernel_launch(void* const* d_in, const int* in_sizes, int n_in,
                              void* d_out, int out_size)
{
    const float* query = (const float*)d_in[0];
    const float* key   = (const float*)d_in[1];
    const float* value = (const float*)d_in[2];
    const int*   mask  = (const int*)  d_in[3];
    const float* Wq    = (const float*)d_in[4];
    const float* bq    = (const float*)d_in[5];
    const float* Wk    = (const float*)d_in[6];
    const float* bk    = (const float*)d_in[7];
    const float* Wv    = (const float*)d_in[8];
    const float* bv    = (const float*)d_in[9];

    float* out  = (float*)d_out;
    float* wbuf = out + (size_t)BB * SS * HH;

    float* vp;
    cudaGetSymbolAddress((void**)&vp, g_v);
    uint32_t* xs;
    cudaGetSymbolAddress((void**)&xs, g_xs);
    uint32_t* ws;
    cudaGetSymbolAddress((void**)&ws, g_ws);

    const size_t XN = (size_t)XROWS * KP;
    const size_t WN = (size_t)HH * KP;

    // 0) Split query/key inputs + Wq/Wk into lossless bf16 triples
    int xb = (int)((XN + 255) / 256);
    int wb = (int)((WN + 255) / 256);
    split3_kernel<<<xb, 256>>>(query, xs,        xs + XN,   xs + 2*XN, (int)XN);
    split3_kernel<<<xb, 256>>>(key,   xs + 3*XN, xs + 4*XN, xs + 5*XN, (int)XN);
    split3_kernel<<<wb, 256>>>(Wq,    ws,        ws + WN,   ws + 2*WN, (int)WN);
    split3_kernel<<<wb, 256>>>(Wk,    ws + 3*WN, ws + 4*WN, ws + 5*WN, (int)WN);

    // 1) q/k projections via 6xBF16 with per-chunk accumulators
    dim3 gProj(HH / 64, XROWS / 128, 2);        // (16, 32, 2)
    proj6_kernel<<<gProj, 256>>>(bq, bk);

    // 1b) v projection via 3xTF32 (error-safe)
    dim3 gProjV(HH / 64, XROWS / 128);          // (16, 32)
    projv_mma_kernel<<<gProjV, 256>>>(value, Wv, bv, vp);

    // 1c) pack v -> fp16 pairs
    pack_v_kernel<<<(QKV_ELEMS / 8) / 256, 256>>>();

    // 2) Scores via 3xTF32 mma.sync (validated)
    cudaFuncSetAttribute(scores_mma_kernel,
                         cudaFuncAttributeMaxDynamicSharedMemorySize,
                         SC_SMEM_BYTES);
    dim3 gScores(SS / 64, SS / 128, BB * NH);   // (32, 16, 32)
    scores_mma_kernel<<<gScores, 256, SC_SMEM_BYTES>>>(mask, wbuf);

    // 3) Softmax + threshold + L1 renorm
    softmax_kernel<<<BB * NH * SS, 256>>>(wbuf);

    // 4) out = w @ v via fp16 mma.sync
    dim3 gAV(SS / 128, BB * NH);
    av_f16_kernel<<<gAV, 256>>>(wbuf, out);
}